// round 1
// baseline (speedup 1.0000x reference)
#include <cuda_runtime.h>
#include <cuda_bf16.h>
#include <cstdint>

#define NN 50000
#define EE 800000
#define FIN 256
#define EMB 128
#define GF 32
#define GG 256
#define NEG_SLOPE 0.2f
#define ETOT (EE + NN)

// ---------------- scratch (device globals; no allocations allowed) -------------
__device__ float g_h[(size_t)NN * EMB];    // pre-aggregation features h = x @ W
__device__ float g_x2[(size_t)NN * EMB];   // layer output (input to next layer)
__device__ float g_as[NN];
__device__ float g_ad[NN];
__device__ int   g_counts[NN];             // counts, then running offsets
__device__ int   g_rowptr[NN + 1];
__device__ int   g_csr_src[ETOT];
__device__ float g_mean[GG * EMB];
__device__ float g_max[GG * EMB];
__device__ float g_wgo[GF * 2];
__device__ float g_bgo[2];

// ---------------- CSR build ----------------------------------------------------
__global__ void k_init_counts() {
    int i = blockIdx.x * blockDim.x + threadIdx.x;
    if (i < NN) g_counts[i] = 1;   // self loop
}

__global__ void k_hist(const int* __restrict__ dst) {
    int e = blockIdx.x * blockDim.x + threadIdx.x;
    if (e < EE) atomicAdd(&g_counts[dst[e]], 1);
}

__global__ void k_scan() {
    __shared__ int sdata[1024];
    __shared__ int s_run;
    int t = threadIdx.x;
    if (t == 0) s_run = 0;
    __syncthreads();
    for (int base = 0; base < NN; base += 1024) {
        int v = (base + t < NN) ? g_counts[base + t] : 0;
        sdata[t] = v;
        __syncthreads();
        for (int off = 1; off < 1024; off <<= 1) {
            int x = (t >= off) ? sdata[t - off] : 0;
            __syncthreads();
            sdata[t] += x;
            __syncthreads();
        }
        int run = s_run;
        if (base + t < NN) g_rowptr[base + t] = run + sdata[t] - v;  // exclusive
        __syncthreads();
        if (t == 1023) s_run = run + sdata[1023];
        __syncthreads();
    }
    if (t == 0) g_rowptr[NN] = s_run;
}

__global__ void k_selfloop() {
    int v = blockIdx.x * blockDim.x + threadIdx.x;
    if (v < NN) {
        int p = g_rowptr[v];
        g_csr_src[p] = v;          // self loop goes first (deterministic)
        g_counts[v] = p + 1;       // running offset for scatter
    }
}

__global__ void k_scatter(const int* __restrict__ src, const int* __restrict__ dst) {
    int e = blockIdx.x * blockDim.x + threadIdx.x;
    if (e < EE) {
        int d = dst[e];
        int pos = atomicAdd(&g_counts[d], 1);
        g_csr_src[pos] = src[e];
    }
}

// ---------------- GEMM: C[M,128] = A[M,K] @ B[K,128], fp32 --------------------
// 64x128 block tile, BK=16, 256 threads, thread tile 8x4.
__global__ __launch_bounds__(256) void k_gemm128(const float* __restrict__ A,
                                                 const float* __restrict__ B,
                                                 float* __restrict__ C,
                                                 int M, int K) {
    __shared__ float As[16][64];
    __shared__ float Bs[16][128];
    int tid = threadIdx.x;
    int m0 = blockIdx.x * 64;
    int tm = tid >> 5;            // 0..7   -> rows tm*8..tm*8+7
    int tn = (tid & 31) << 2;     // 0..124 -> cols tn..tn+3
    int ar = tid >> 2, ak = (tid & 3) << 2;     // A tile load
    int br = tid >> 4, bc = (tid & 15) << 3;    // B tile load

    float acc[8][4];
#pragma unroll
    for (int i = 0; i < 8; i++)
#pragma unroll
        for (int j = 0; j < 4; j++) acc[i][j] = 0.f;

    for (int k0 = 0; k0 < K; k0 += 16) {
        float4 a4 = make_float4(0.f, 0.f, 0.f, 0.f);
        int row = m0 + ar;
        if (row < M) a4 = *(const float4*)&A[(size_t)row * K + k0 + ak];
        As[ak + 0][ar] = a4.x;
        As[ak + 1][ar] = a4.y;
        As[ak + 2][ar] = a4.z;
        As[ak + 3][ar] = a4.w;
        float4 b0 = *(const float4*)&B[(size_t)(k0 + br) * 128 + bc];
        float4 b1 = *(const float4*)&B[(size_t)(k0 + br) * 128 + bc + 4];
        *(float4*)&Bs[br][bc] = b0;
        *(float4*)&Bs[br][bc + 4] = b1;
        __syncthreads();
#pragma unroll
        for (int k = 0; k < 16; k++) {
            float bq[4];
            *(float4*)bq = *(float4*)&Bs[k][tn];
            float av[8];
#pragma unroll
            for (int i = 0; i < 8; i++) av[i] = As[k][tm * 8 + i];
#pragma unroll
            for (int i = 0; i < 8; i++) {
                acc[i][0] += av[i] * bq[0];
                acc[i][1] += av[i] * bq[1];
                acc[i][2] += av[i] * bq[2];
                acc[i][3] += av[i] * bq[3];
            }
        }
        __syncthreads();
    }
#pragma unroll
    for (int i = 0; i < 8; i++) {
        int row = m0 + tm * 8 + i;
        if (row < M) {
            float4 o = make_float4(acc[i][0], acc[i][1], acc[i][2], acc[i][3]);
            *(float4*)&C[(size_t)row * 128 + tn] = o;
        }
    }
}

// ---------------- per-node attention dots: as = h.a_src, ad = h.a_dst ----------
__global__ __launch_bounds__(256) void k_attn_dots(const float* __restrict__ h,
                                                   const float* __restrict__ a_src,
                                                   const float* __restrict__ a_dst) {
    int wid = (blockIdx.x * blockDim.x + threadIdx.x) >> 5;
    int lane = threadIdx.x & 31;
    if (wid >= NN) return;
    float4 hv = *(const float4*)&h[(size_t)wid * 128 + lane * 4];
    float4 s4 = *(const float4*)&a_src[lane * 4];
    float4 d4 = *(const float4*)&a_dst[lane * 4];
    float ps = hv.x * s4.x + hv.y * s4.y + hv.z * s4.z + hv.w * s4.w;
    float pd = hv.x * d4.x + hv.y * d4.y + hv.z * d4.z + hv.w * d4.w;
#pragma unroll
    for (int off = 16; off > 0; off >>= 1) {
        ps += __shfl_xor_sync(0xFFFFFFFF, ps, off);
        pd += __shfl_xor_sync(0xFFFFFFFF, pd, off);
    }
    if (lane == 0) {
        g_as[wid] = ps;
        g_ad[wid] = pd;
    }
}

__device__ __forceinline__ float lrelu(float x) {
    return x > 0.f ? x : NEG_SLOPE * x;
}

// ---------------- gather-side softmax aggregation ------------------------------
// warp per destination node; out[v] = sum_j alpha_j * h[src_j] + b
__global__ __launch_bounds__(256) void k_aggregate(const float* __restrict__ h,
                                                   const float* __restrict__ b,
                                                   float* __restrict__ out) {
    int v = (blockIdx.x * blockDim.x + threadIdx.x) >> 5;
    int lane = threadIdx.x & 31;
    if (v >= NN) return;
    int beg = g_rowptr[v];
    int end = g_rowptr[v + 1];
    float adv = g_ad[v];

    // pass 1: max
    float m = -1e30f;
    for (int j = beg + lane; j < end; j += 32) {
        float e = lrelu(g_as[g_csr_src[j]] + adv);
        m = fmaxf(m, e);
    }
#pragma unroll
    for (int off = 16; off > 0; off >>= 1)
        m = fmaxf(m, __shfl_xor_sync(0xFFFFFFFF, m, off));

    // pass 2: denominator
    float den = 0.f;
    for (int j = beg + lane; j < end; j += 32) {
        float e = lrelu(g_as[g_csr_src[j]] + adv);
        den += __expf(e - m);
    }
#pragma unroll
    for (int off = 16; off > 0; off >>= 1)
        den += __shfl_xor_sync(0xFFFFFFFF, den, off);

    // pass 3: weighted accumulate (edge-serial, feature-parallel)
    float4 acc = make_float4(0.f, 0.f, 0.f, 0.f);
    for (int j = beg; j < end; j++) {
        int s = g_csr_src[j];
        float e = lrelu(g_as[s] + adv);
        float w = __expf(e - m);
        float4 hv = *(const float4*)&h[(size_t)s * 128 + lane * 4];
        acc.x += w * hv.x;
        acc.y += w * hv.y;
        acc.z += w * hv.z;
        acc.w += w * hv.w;
    }
    float inv = 1.f / den;
    float4 b4 = *(const float4*)&b[lane * 4];
    float4 o = make_float4(acc.x * inv + b4.x, acc.y * inv + b4.y,
                           acc.z * inv + b4.z, acc.w * inv + b4.w);
    *(float4*)&out[(size_t)v * 128 + lane * 4] = o;
}

// ---------------- pooling (block per graph, binary search on sorted batch) -----
__device__ __forceinline__ int lower_bound_i(const int* a, int n, int key) {
    int lo = 0, hi = n;
    while (lo < hi) {
        int mid = (lo + hi) >> 1;
        if (a[mid] < key) lo = mid + 1;
        else hi = mid;
    }
    return lo;
}

__global__ __launch_bounds__(128) void k_pool(const float* __restrict__ x,
                                              const int* __restrict__ batch) {
    int g = blockIdx.x;
    int f = threadIdx.x;
    __shared__ int s_lo, s_hi;
    if (f == 0) s_lo = lower_bound_i(batch, NN, g);
    if (f == 1) s_hi = lower_bound_i(batch, NN, g + 1);
    __syncthreads();
    int lo = s_lo, hi = s_hi;
    float s = 0.f, mx = -1e30f;
    for (int i = lo; i < hi; i++) {
        float v = x[(size_t)i * 128 + f];
        s += v;
        mx = fmaxf(mx, v);
    }
    int cnt = hi - lo;
    g_mean[g * 128 + f] = s / (float)max(cnt, 1);
    g_max[g * 128 + f] = (cnt > 0) ? mx : 0.f;
}

// ---------------- fold g-feature path: wgo = Wg @ Wo[256:384], bgo = bg@.. + bo -
__global__ void k_fold(const float* __restrict__ Wg, const float* __restrict__ bg,
                       const float* __restrict__ Wo, const float* __restrict__ bo) {
    int t = threadIdx.x;
    if (t < GF * 2) {
        int k = t >> 1, c = t & 1;
        float s = 0.f;
        for (int j = 0; j < EMB; j++)
            s += Wg[k * EMB + j] * Wo[(256 + j) * 2 + c];
        g_wgo[t] = s;
    } else if (t < GF * 2 + 2) {
        int c = t - GF * 2;
        float s = bo[c];
        for (int j = 0; j < EMB; j++)
            s += bg[j] * Wo[(256 + j) * 2 + c];
        g_bgo[c] = s;
    }
}

// ---------------- head: logits + log_softmax, warp per graph -------------------
__global__ __launch_bounds__(256) void k_head(const float* __restrict__ gfeat,
                                              const float* __restrict__ Wo,
                                              float* __restrict__ out) {
    int g = (blockIdx.x * blockDim.x + threadIdx.x) >> 5;
    int lane = threadIdx.x & 31;
    if (g >= GG) return;
    float s0 = 0.f, s1 = 0.f;
#pragma unroll
    for (int j = lane; j < 128; j += 32) {
        float mn = g_mean[g * 128 + j];
        float mx = g_max[g * 128 + j];
        s0 += mn * Wo[j * 2 + 0] + mx * Wo[(128 + j) * 2 + 0];
        s1 += mn * Wo[j * 2 + 1] + mx * Wo[(128 + j) * 2 + 1];
    }
    float gv = gfeat[g * GF + lane];
    s0 += gv * g_wgo[lane * 2 + 0];
    s1 += gv * g_wgo[lane * 2 + 1];
#pragma unroll
    for (int off = 16; off > 0; off >>= 1) {
        s0 += __shfl_xor_sync(0xFFFFFFFF, s0, off);
        s1 += __shfl_xor_sync(0xFFFFFFFF, s1, off);
    }
    if (lane == 0) {
        float l0 = s0 + g_bgo[0];
        float l1 = s1 + g_bgo[1];
        float m = fmaxf(l0, l1);
        float lse = m + logf(expf(l0 - m) + expf(l1 - m));
        out[g * 2 + 0] = l0 - lse;
        out[g * 2 + 1] = l1 - lse;
    }
}

// ---------------- launch --------------------------------------------------------
extern "C" void kernel_launch(void* const* d_in, const int* in_sizes, int n_in,
                              void* d_out, int out_size) {
    const float* x      = (const float*)d_in[0];
    const int*   edges  = (const int*)d_in[1];     // [2, E]
    const int*   batch  = (const int*)d_in[2];
    const float* gfeat  = (const float*)d_in[3];
    const float* W1     = (const float*)d_in[4];
    const float* a1s    = (const float*)d_in[5];
    const float* a1d    = (const float*)d_in[6];
    const float* b1     = (const float*)d_in[7];
    const float* W2     = (const float*)d_in[8];
    const float* a2s    = (const float*)d_in[9];
    const float* a2d    = (const float*)d_in[10];
    const float* b2     = (const float*)d_in[11];
    const float* Wg     = (const float*)d_in[12];
    const float* bg     = (const float*)d_in[13];
    const float* Wo     = (const float*)d_in[14];
    const float* bo     = (const float*)d_in[15];
    float* out = (float*)d_out;

    const int* src = edges;
    const int* dst = edges + EE;

    float* d_h;  cudaGetSymbolAddress((void**)&d_h,  g_h);
    float* d_x2; cudaGetSymbolAddress((void**)&d_x2, g_x2);

    // CSR build (same for both layers)
    k_init_counts<<<(NN + 255) / 256, 256>>>();
    k_hist<<<(EE + 255) / 256, 256>>>(dst);
    k_scan<<<1, 1024>>>();
    k_selfloop<<<(NN + 255) / 256, 256>>>();
    k_scatter<<<(EE + 255) / 256, 256>>>(src, dst);

    int gemm_blocks = (NN + 63) / 64;
    int warp_blocks = (NN * 32 + 255) / 256;

    // layer 1
    k_gemm128<<<gemm_blocks, 256>>>(x, W1, d_h, NN, FIN);
    k_attn_dots<<<warp_blocks, 256>>>(d_h, a1s, a1d);
    k_aggregate<<<warp_blocks, 256>>>(d_h, b1, d_x2);

    // layer 2
    k_gemm128<<<gemm_blocks, 256>>>(d_x2, W2, d_h, NN, EMB);
    k_attn_dots<<<warp_blocks, 256>>>(d_h, a2s, a2d);
    k_aggregate<<<warp_blocks, 256>>>(d_h, b2, d_x2);

    // pooling + head
    k_pool<<<GG, 128>>>(d_x2, batch);
    k_fold<<<1, 96>>>(Wg, bg, Wo, bo);
    k_head<<<(GG * 32 + 255) / 256, 256>>>(gfeat, Wo, out);
}

// round 2
// speedup vs baseline: 1.4471x; 1.4471x over previous
#include <cuda_runtime.h>
#include <cuda_bf16.h>
#include <cstdint>

#define NN 50000
#define EE 800000
#define FIN 256
#define EMB 128
#define GF 32
#define GG 256
#define NEG_SLOPE 0.2f
#define ETOT (EE + NN)

// ---------------- scratch (device globals; no allocations allowed) -------------
__device__ float g_h[(size_t)NN * EMB];    // pre-aggregation features h = x @ W
__device__ float g_x2[(size_t)NN * EMB];   // layer output (input to next layer)
__device__ float g_as[NN];
__device__ float g_ad[NN];
__device__ int   g_counts[NN];             // counts, then running offsets
__device__ int   g_rowptr[NN + 1];
__device__ int   g_csr_src[ETOT];
__device__ float g_mean[GG * EMB];
__device__ float g_max[GG * EMB];
__device__ float g_wgo[GF * 2];
__device__ float g_bgo[2];

// ---------------- CSR build ----------------------------------------------------
__global__ void k_init_counts() {
    int i = blockIdx.x * blockDim.x + threadIdx.x;
    if (i < NN) g_counts[i] = 1;   // self loop
}

__global__ void k_hist(const int* __restrict__ dst) {
    int e = blockIdx.x * blockDim.x + threadIdx.x;
    if (e < EE) atomicAdd(&g_counts[dst[e]], 1);
}

// shuffle-based single-block scan: 3 barriers per 1024-chunk
__global__ void k_scan() {
    __shared__ int warp_sums[32];
    __shared__ int s_run;
    int t = threadIdx.x;
    int lane = t & 31, w = t >> 5;
    if (t == 0) s_run = 0;
    __syncthreads();
    for (int base = 0; base < NN; base += 1024) {
        int i = base + t;
        int v = (i < NN) ? g_counts[i] : 0;
        int x = v;
#pragma unroll
        for (int off = 1; off < 32; off <<= 1) {
            int y = __shfl_up_sync(0xFFFFFFFF, x, off);
            if (lane >= off) x += y;
        }
        if (lane == 31) warp_sums[w] = x;
        __syncthreads();
        if (w == 0) {
            int s = warp_sums[lane];
#pragma unroll
            for (int off = 1; off < 32; off <<= 1) {
                int y = __shfl_up_sync(0xFFFFFFFF, s, off);
                if (lane >= off) s += y;
            }
            warp_sums[lane] = s;
        }
        __syncthreads();
        int run = s_run;
        if (i < NN) g_rowptr[i] = run + (w > 0 ? warp_sums[w - 1] : 0) + x - v;
        __syncthreads();
        if (t == 0) s_run = run + warp_sums[31];
        __syncthreads();
    }
    if (threadIdx.x == 0) g_rowptr[NN] = s_run;
}

__global__ void k_selfloop() {
    int v = blockIdx.x * blockDim.x + threadIdx.x;
    if (v < NN) {
        int p = g_rowptr[v];
        g_csr_src[p] = v;          // self loop goes first (deterministic)
        g_counts[v] = p + 1;       // running offset for scatter
    }
}

__global__ void k_scatter(const int* __restrict__ src, const int* __restrict__ dst) {
    int e = blockIdx.x * blockDim.x + threadIdx.x;
    if (e < EE) {
        int d = dst[e];
        int pos = atomicAdd(&g_counts[d], 1);
        g_csr_src[pos] = src[e];
    }
}

// ---------------- tf32 tensor-core GEMM: C[M,128] = A[M,K] @ B[K,128] ---------
__device__ __forceinline__ uint32_t f2tf32(float x) {
    uint32_t r;
    asm("cvt.rna.tf32.f32 %0, %1;" : "=r"(r) : "f"(x));
    return r;
}

__device__ __forceinline__ void mma_tf32(float* c, const uint32_t* a, const uint32_t* b) {
    asm volatile(
        "mma.sync.aligned.m16n8k8.row.col.f32.tf32.tf32.f32 "
        "{%0,%1,%2,%3}, {%4,%5,%6,%7}, {%8,%9}, {%0,%1,%2,%3};\n"
        : "+f"(c[0]), "+f"(c[1]), "+f"(c[2]), "+f"(c[3])
        : "r"(a[0]), "r"(a[1]), "r"(a[2]), "r"(a[3]), "r"(b[0]), "r"(b[1]));
}

#define BM 128
#define BKQ 16
#define AP 20    // A smem stride (floats): bank = (20r+k)%32 conflict-free
#define BP 132   // B smem stride: bank = (132k+n)%32 = (4k+n)%32 conflict-free

__global__ __launch_bounds__(256) void k_gemm_tc(const float* __restrict__ A,
                                                 const float* __restrict__ B,
                                                 float* __restrict__ C,
                                                 int M, int K) {
    __shared__ uint32_t As[2][BM][AP];
    __shared__ uint32_t Bs[2][BKQ][BP];
    int tid = threadIdx.x;
    int lane = tid & 31, wid = tid >> 5;
    int wm = wid >> 2;        // 0..1 -> 64-row slab
    int wn = wid & 3;         // 0..3 -> 32-col slab
    int g = lane >> 2, kk = lane & 3;
    int m0 = blockIdx.x * BM;

    // global load mapping
    int arow = tid >> 2;            // 0..63 (two passes: +0, +64)
    int acol = (tid & 3) << 2;      // 0,4,8,12
    int brow = tid >> 5;            // 0..7 (two passes: +0, +8)
    int bcol = (tid & 31) << 2;     // 0..124

    float c[4][4][4];
#pragma unroll
    for (int mt = 0; mt < 4; mt++)
#pragma unroll
        for (int nt = 0; nt < 4; nt++)
#pragma unroll
            for (int i = 0; i < 4; i++) c[mt][nt][i] = 0.f;

    float4 ra[2], rb[2];
    const int nch = K / BKQ;

    // --- prologue: fetch chunk 0 ---
    {
        int r0 = m0 + arow, r1 = m0 + arow + 64;
        ra[0] = (r0 < M) ? *(const float4*)&A[(size_t)r0 * K + acol] : make_float4(0, 0, 0, 0);
        ra[1] = (r1 < M) ? *(const float4*)&A[(size_t)r1 * K + acol] : make_float4(0, 0, 0, 0);
        rb[0] = *(const float4*)&B[(size_t)brow * 128 + bcol];
        rb[1] = *(const float4*)&B[(size_t)(brow + 8) * 128 + bcol];
    }
    {
        uint32_t* pa0 = &As[0][arow][acol];
        pa0[0] = f2tf32(ra[0].x); pa0[1] = f2tf32(ra[0].y); pa0[2] = f2tf32(ra[0].z); pa0[3] = f2tf32(ra[0].w);
        uint32_t* pa1 = &As[0][arow + 64][acol];
        pa1[0] = f2tf32(ra[1].x); pa1[1] = f2tf32(ra[1].y); pa1[2] = f2tf32(ra[1].z); pa1[3] = f2tf32(ra[1].w);
        uint32_t* pb0 = &Bs[0][brow][bcol];
        pb0[0] = f2tf32(rb[0].x); pb0[1] = f2tf32(rb[0].y); pb0[2] = f2tf32(rb[0].z); pb0[3] = f2tf32(rb[0].w);
        uint32_t* pb1 = &Bs[0][brow + 8][bcol];
        pb1[0] = f2tf32(rb[1].x); pb1[1] = f2tf32(rb[1].y); pb1[2] = f2tf32(rb[1].z); pb1[3] = f2tf32(rb[1].w);
    }
    __syncthreads();

    for (int c0 = 0; c0 < nch; c0++) {
        int cur = c0 & 1;
        if (c0 + 1 < nch) {
            int k0 = (c0 + 1) * BKQ;
            int r0 = m0 + arow, r1 = m0 + arow + 64;
            ra[0] = (r0 < M) ? *(const float4*)&A[(size_t)r0 * K + k0 + acol] : make_float4(0, 0, 0, 0);
            ra[1] = (r1 < M) ? *(const float4*)&A[(size_t)r1 * K + k0 + acol] : make_float4(0, 0, 0, 0);
            rb[0] = *(const float4*)&B[(size_t)(k0 + brow) * 128 + bcol];
            rb[1] = *(const float4*)&B[(size_t)(k0 + brow + 8) * 128 + bcol];
        }
#pragma unroll
        for (int ks = 0; ks < 2; ks++) {
            int kb = ks * 8;
            uint32_t af[4][4], bf[4][2];
#pragma unroll
            for (int mt = 0; mt < 4; mt++) {
                int row = wm * 64 + mt * 16 + g;
                af[mt][0] = As[cur][row][kb + kk];
                af[mt][1] = As[cur][row + 8][kb + kk];
                af[mt][2] = As[cur][row][kb + kk + 4];
                af[mt][3] = As[cur][row + 8][kb + kk + 4];
            }
#pragma unroll
            for (int nt = 0; nt < 4; nt++) {
                int col = wn * 32 + nt * 8 + g;
                bf[nt][0] = Bs[cur][kb + kk][col];
                bf[nt][1] = Bs[cur][kb + kk + 4][col];
            }
#pragma unroll
            for (int mt = 0; mt < 4; mt++)
#pragma unroll
                for (int nt = 0; nt < 4; nt++)
                    mma_tf32(c[mt][nt], af[mt], bf[nt]);
        }
        if (c0 + 1 < nch) {
            int nb = (c0 + 1) & 1;
            uint32_t* pa0 = &As[nb][arow][acol];
            pa0[0] = f2tf32(ra[0].x); pa0[1] = f2tf32(ra[0].y); pa0[2] = f2tf32(ra[0].z); pa0[3] = f2tf32(ra[0].w);
            uint32_t* pa1 = &As[nb][arow + 64][acol];
            pa1[0] = f2tf32(ra[1].x); pa1[1] = f2tf32(ra[1].y); pa1[2] = f2tf32(ra[1].z); pa1[3] = f2tf32(ra[1].w);
            uint32_t* pb0 = &Bs[nb][brow][bcol];
            pb0[0] = f2tf32(rb[0].x); pb0[1] = f2tf32(rb[0].y); pb0[2] = f2tf32(rb[0].z); pb0[3] = f2tf32(rb[0].w);
            uint32_t* pb1 = &Bs[nb][brow + 8][bcol];
            pb1[0] = f2tf32(rb[1].x); pb1[1] = f2tf32(rb[1].y); pb1[2] = f2tf32(rb[1].z); pb1[3] = f2tf32(rb[1].w);
            __syncthreads();
        }
    }

    // epilogue
#pragma unroll
    for (int mt = 0; mt < 4; mt++) {
        int row = m0 + wm * 64 + mt * 16 + g;
#pragma unroll
        for (int nt = 0; nt < 4; nt++) {
            int col = wn * 32 + nt * 8 + kk * 2;
            if (row < M)
                *(float2*)&C[(size_t)row * 128 + col] = make_float2(c[mt][nt][0], c[mt][nt][1]);
            if (row + 8 < M)
                *(float2*)&C[(size_t)(row + 8) * 128 + col] = make_float2(c[mt][nt][2], c[mt][nt][3]);
        }
    }
}

// ---------------- per-node attention dots: as = h.a_src, ad = h.a_dst ----------
__global__ __launch_bounds__(256) void k_attn_dots(const float* __restrict__ h,
                                                   const float* __restrict__ a_src,
                                                   const float* __restrict__ a_dst) {
    int wid = (blockIdx.x * blockDim.x + threadIdx.x) >> 5;
    int lane = threadIdx.x & 31;
    if (wid >= NN) return;
    float4 hv = *(const float4*)&h[(size_t)wid * 128 + lane * 4];
    float4 s4 = *(const float4*)&a_src[lane * 4];
    float4 d4 = *(const float4*)&a_dst[lane * 4];
    float ps = hv.x * s4.x + hv.y * s4.y + hv.z * s4.z + hv.w * s4.w;
    float pd = hv.x * d4.x + hv.y * d4.y + hv.z * d4.z + hv.w * d4.w;
#pragma unroll
    for (int off = 16; off > 0; off >>= 1) {
        ps += __shfl_xor_sync(0xFFFFFFFF, ps, off);
        pd += __shfl_xor_sync(0xFFFFFFFF, pd, off);
    }
    if (lane == 0) {
        g_as[wid] = ps;
        g_ad[wid] = pd;
    }
}

__device__ __forceinline__ float lrelu(float x) {
    return x > 0.f ? x : NEG_SLOPE * x;
}

// ---------------- gather-side softmax aggregation ------------------------------
__global__ __launch_bounds__(256) void k_aggregate(const float* __restrict__ h,
                                                   const float* __restrict__ b,
                                                   float* __restrict__ out) {
    int v = (blockIdx.x * blockDim.x + threadIdx.x) >> 5;
    int lane = threadIdx.x & 31;
    if (v >= NN) return;
    int beg = g_rowptr[v];
    int end = g_rowptr[v + 1];
    float adv = g_ad[v];

    float m = -1e30f;
    for (int j = beg + lane; j < end; j += 32) {
        float e = lrelu(g_as[g_csr_src[j]] + adv);
        m = fmaxf(m, e);
    }
#pragma unroll
    for (int off = 16; off > 0; off >>= 1)
        m = fmaxf(m, __shfl_xor_sync(0xFFFFFFFF, m, off));

    float den = 0.f;
    for (int j = beg + lane; j < end; j += 32) {
        float e = lrelu(g_as[g_csr_src[j]] + adv);
        den += __expf(e - m);
    }
#pragma unroll
    for (int off = 16; off > 0; off >>= 1)
        den += __shfl_xor_sync(0xFFFFFFFF, den, off);

    float4 acc = make_float4(0.f, 0.f, 0.f, 0.f);
    for (int j = beg; j < end; j++) {
        int s = g_csr_src[j];
        float e = lrelu(g_as[s] + adv);
        float w = __expf(e - m);
        float4 hv = *(const float4*)&h[(size_t)s * 128 + lane * 4];
        acc.x += w * hv.x;
        acc.y += w * hv.y;
        acc.z += w * hv.z;
        acc.w += w * hv.w;
    }
    float inv = 1.f / den;
    float4 b4 = *(const float4*)&b[lane * 4];
    float4 o = make_float4(acc.x * inv + b4.x, acc.y * inv + b4.y,
                           acc.z * inv + b4.z, acc.w * inv + b4.w);
    *(float4*)&out[(size_t)v * 128 + lane * 4] = o;
}

// ---------------- pooling ------------------------------------------------------
__device__ __forceinline__ int lower_bound_i(const int* a, int n, int key) {
    int lo = 0, hi = n;
    while (lo < hi) {
        int mid = (lo + hi) >> 1;
        if (a[mid] < key) lo = mid + 1;
        else hi = mid;
    }
    return lo;
}

__global__ __launch_bounds__(128) void k_pool(const float* __restrict__ x,
                                              const int* __restrict__ batch) {
    int g = blockIdx.x;
    int f = threadIdx.x;
    __shared__ int s_lo, s_hi;
    if (f == 0) s_lo = lower_bound_i(batch, NN, g);
    if (f == 1) s_hi = lower_bound_i(batch, NN, g + 1);
    __syncthreads();
    int lo = s_lo, hi = s_hi;
    float s = 0.f, mx = -1e30f;
    for (int i = lo; i < hi; i++) {
        float v = x[(size_t)i * 128 + f];
        s += v;
        mx = fmaxf(mx, v);
    }
    int cnt = hi - lo;
    g_mean[g * 128 + f] = s / (float)max(cnt, 1);
    g_max[g * 128 + f] = (cnt > 0) ? mx : 0.f;
}

// ---------------- fold g-feature path ------------------------------------------
__global__ void k_fold(const float* __restrict__ Wg, const float* __restrict__ bg,
                       const float* __restrict__ Wo, const float* __restrict__ bo) {
    int t = threadIdx.x;
    if (t < GF * 2) {
        int k = t >> 1, c = t & 1;
        float s = 0.f;
        for (int j = 0; j < EMB; j++)
            s += Wg[k * EMB + j] * Wo[(256 + j) * 2 + c];
        g_wgo[t] = s;
    } else if (t < GF * 2 + 2) {
        int c = t - GF * 2;
        float s = bo[c];
        for (int j = 0; j < EMB; j++)
            s += bg[j] * Wo[(256 + j) * 2 + c];
        g_bgo[c] = s;
    }
}

// ---------------- head ---------------------------------------------------------
__global__ __launch_bounds__(256) void k_head(const float* __restrict__ gfeat,
                                              const float* __restrict__ Wo,
                                              float* __restrict__ out) {
    int g = (blockIdx.x * blockDim.x + threadIdx.x) >> 5;
    int lane = threadIdx.x & 31;
    if (g >= GG) return;
    float s0 = 0.f, s1 = 0.f;
#pragma unroll
    for (int j = lane; j < 128; j += 32) {
        float mn = g_mean[g * 128 + j];
        float mx = g_max[g * 128 + j];
        s0 += mn * Wo[j * 2 + 0] + mx * Wo[(128 + j) * 2 + 0];
        s1 += mn * Wo[j * 2 + 1] + mx * Wo[(128 + j) * 2 + 1];
    }
    float gv = gfeat[g * GF + lane];
    s0 += gv * g_wgo[lane * 2 + 0];
    s1 += gv * g_wgo[lane * 2 + 1];
#pragma unroll
    for (int off = 16; off > 0; off >>= 1) {
        s0 += __shfl_xor_sync(0xFFFFFFFF, s0, off);
        s1 += __shfl_xor_sync(0xFFFFFFFF, s1, off);
    }
    if (lane == 0) {
        float l0 = s0 + g_bgo[0];
        float l1 = s1 + g_bgo[1];
        float m = fmaxf(l0, l1);
        float lse = m + logf(expf(l0 - m) + expf(l1 - m));
        out[g * 2 + 0] = l0 - lse;
        out[g * 2 + 1] = l1 - lse;
    }
}

// ---------------- launch --------------------------------------------------------
extern "C" void kernel_launch(void* const* d_in, const int* in_sizes, int n_in,
                              void* d_out, int out_size) {
    const float* x      = (const float*)d_in[0];
    const int*   edges  = (const int*)d_in[1];     // [2, E]
    const int*   batch  = (const int*)d_in[2];
    const float* gfeat  = (const float*)d_in[3];
    const float* W1     = (const float*)d_in[4];
    const float* a1s    = (const float*)d_in[5];
    const float* a1d    = (const float*)d_in[6];
    const float* b1     = (const float*)d_in[7];
    const float* W2     = (const float*)d_in[8];
    const float* a2s    = (const float*)d_in[9];
    const float* a2d    = (const float*)d_in[10];
    const float* b2     = (const float*)d_in[11];
    const float* Wg     = (const float*)d_in[12];
    const float* bg     = (const float*)d_in[13];
    const float* Wo     = (const float*)d_in[14];
    const float* bo     = (const float*)d_in[15];
    float* out = (float*)d_out;

    const int* src = edges;
    const int* dst = edges + EE;

    float* d_h;  cudaGetSymbolAddress((void**)&d_h,  g_h);
    float* d_x2; cudaGetSymbolAddress((void**)&d_x2, g_x2);

    // CSR build
    k_init_counts<<<(NN + 255) / 256, 256>>>();
    k_hist<<<(EE + 255) / 256, 256>>>(dst);
    k_scan<<<1, 1024>>>();
    k_selfloop<<<(NN + 255) / 256, 256>>>();
    k_scatter<<<(EE + 255) / 256, 256>>>(src, dst);

    int gemm_blocks = (NN + BM - 1) / BM;
    int warp_blocks = (NN * 32 + 255) / 256;

    // layer 1
    k_gemm_tc<<<gemm_blocks, 256>>>(x, W1, d_h, NN, FIN);
    k_attn_dots<<<warp_blocks, 256>>>(d_h, a1s, a1d);
    k_aggregate<<<warp_blocks, 256>>>(d_h, b1, d_x2);

    // layer 2
    k_gemm_tc<<<gemm_blocks, 256>>>(d_x2, W2, d_h, NN, EMB);
    k_attn_dots<<<warp_blocks, 256>>>(d_h, a2s, a2d);
    k_aggregate<<<warp_blocks, 256>>>(d_h, b2, d_x2);

    // pooling + head
    k_pool<<<GG, 128>>>(d_x2, batch);
    k_fold<<<1, 96>>>(Wg, bg, Wo, bo);
    k_head<<<(GG * 32 + 255) / 256, 256>>>(gfeat, Wo, out);
}

// round 5
// speedup vs baseline: 1.5300x; 1.0573x over previous
#include <cuda_runtime.h>
#include <cuda_bf16.h>
#include <cstdint>

#define NN 50000
#define EE 800000
#define FIN 256
#define EMB 128
#define GF 32
#define GG 256
#define NEG_SLOPE 0.2f
#define ETOT (EE + NN)

// ---------------- scratch (device globals; no allocations allowed) -------------
__device__ float g_h[(size_t)NN * EMB];    // pre-aggregation features h = x @ W
__device__ float g_x2[(size_t)NN * EMB];   // layer output (input to next layer)
__device__ float g_as[NN];
__device__ float g_ad[NN];
__device__ int   g_counts[NN];             // edge histogram, then scatter cursors
__device__ int   g_rowptr[NN + 1];
__device__ int   g_csr_src[ETOT];
__device__ float g_mean[GG * EMB];
__device__ float g_max[GG * EMB];
__device__ float g_wgo[GF * 2];
__device__ float g_bgo[2];

// ---------------- CSR build ----------------------------------------------------
__global__ void k_zero() {
    int i = blockIdx.x * blockDim.x + threadIdx.x;
    if (i < NN) g_counts[i] = 0;
}

__global__ void k_hist(const int* __restrict__ dst) {
    int e = blockIdx.x * blockDim.x + threadIdx.x;
    if (e < EE) atomicAdd(&g_counts[dst[e]], 1);
}

// single-block shuffle scan; deg(v) = g_counts[v] + 1 (self loop).
// writes rowptr (exclusive) and counts[v] = rowptr[v]+1 (scatter cursor past self-loop slot)
__global__ void k_scan() {
    __shared__ int warp_sums[32];
    __shared__ int s_run;
    int t = threadIdx.x;
    int lane = t & 31, w = t >> 5;
    if (t == 0) s_run = 0;
    __syncthreads();
    for (int base = 0; base < NN; base += 1024) {
        int i = base + t;
        int v = (i < NN) ? (g_counts[i] + 1) : 0;
        int x = v;
#pragma unroll
        for (int off = 1; off < 32; off <<= 1) {
            int y = __shfl_up_sync(0xFFFFFFFF, x, off);
            if (lane >= off) x += y;
        }
        if (lane == 31) warp_sums[w] = x;
        __syncthreads();
        if (w == 0) {
            int s = warp_sums[lane];
#pragma unroll
            for (int off = 1; off < 32; off <<= 1) {
                int y = __shfl_up_sync(0xFFFFFFFF, s, off);
                if (lane >= off) s += y;
            }
            warp_sums[lane] = s;
        }
        __syncthreads();
        int run = s_run;
        if (i < NN) {
            int excl = run + (w > 0 ? warp_sums[w - 1] : 0) + x - v;
            g_rowptr[i] = excl;
            g_counts[i] = excl + 1;   // scatter cursor (slot excl reserved for self loop)
        }
        __syncthreads();
        if (t == 0) s_run = run + warp_sums[31];
        __syncthreads();
    }
    if (threadIdx.x == 0) g_rowptr[NN] = s_run;
}

// self-loop fill + edge scatter in one kernel (disjoint slots, no ordering needed)
__global__ void k_fill(const int* __restrict__ src, const int* __restrict__ dst) {
    int t = blockIdx.x * blockDim.x + threadIdx.x;
    if (t < NN) {
        g_csr_src[g_rowptr[t]] = t;
    } else if (t < NN + EE) {
        int e = t - NN;
        int d = dst[e];
        int pos = atomicAdd(&g_counts[d], 1);
        g_csr_src[pos] = src[e];
    }
}

// ---------------- tf32 tensor-core GEMM + fused attention dots -----------------
__device__ __forceinline__ uint32_t f2tf32(float x) {
    uint32_t r;
    asm("cvt.rna.tf32.f32 %0, %1;" : "=r"(r) : "f"(x));
    return r;
}

__device__ __forceinline__ void mma_tf32(float* c, const uint32_t* a, const uint32_t* b) {
    asm volatile(
        "mma.sync.aligned.m16n8k8.row.col.f32.tf32.tf32.f32 "
        "{%0,%1,%2,%3}, {%4,%5,%6,%7}, {%8,%9}, {%0,%1,%2,%3};\n"
        : "+f"(c[0]), "+f"(c[1]), "+f"(c[2]), "+f"(c[3])
        : "r"(a[0]), "r"(a[1]), "r"(a[2]), "r"(a[3]), "r"(b[0]), "r"(b[1]));
}

#define BM 128
#define BKQ 16
#define AP 20    // A smem stride (floats): bank = (20r+k)%32 conflict-free
#define BP 132   // B smem stride: bank = (132k+n)%32 = (4k+n)%32 conflict-free

__global__ __launch_bounds__(256) void k_gemm_tc(const float* __restrict__ A,
                                                 const float* __restrict__ B,
                                                 float* __restrict__ C,
                                                 const float* __restrict__ a_src,
                                                 const float* __restrict__ a_dst,
                                                 int M, int K) {
    __shared__ uint32_t As[2][BM][AP];
    __shared__ uint32_t Bs[2][BKQ][BP];
    __shared__ float s_av[2][128];
    __shared__ float s_pa[128][2];
    int tid = threadIdx.x;
    int lane = tid & 31, wid = tid >> 5;
    int wm = wid >> 2;        // 0..1 -> 64-row slab
    int wn = wid & 3;         // 0..3 -> 32-col slab
    int g = lane >> 2, kk = lane & 3;
    int m0 = blockIdx.x * BM;

    if (tid < 128) {
        s_av[0][tid] = a_src[tid];
        s_pa[tid][0] = 0.f;
        s_pa[tid][1] = 0.f;
    } else {
        s_av[1][tid - 128] = a_dst[tid - 128];
    }

    int arow = tid >> 2;            // 0..63 (two passes: +0, +64)
    int acol = (tid & 3) << 2;      // 0,4,8,12
    int brow = tid >> 5;            // 0..7 (two passes: +0, +8)
    int bcol = (tid & 31) << 2;     // 0..124

    float c[4][4][4];
#pragma unroll
    for (int mt = 0; mt < 4; mt++)
#pragma unroll
        for (int nt = 0; nt < 4; nt++)
#pragma unroll
            for (int i = 0; i < 4; i++) c[mt][nt][i] = 0.f;

    float4 ra[2], rb[2];
    const int nch = K / BKQ;

    {
        int r0 = m0 + arow, r1 = m0 + arow + 64;
        ra[0] = (r0 < M) ? *(const float4*)&A[(size_t)r0 * K + acol] : make_float4(0, 0, 0, 0);
        ra[1] = (r1 < M) ? *(const float4*)&A[(size_t)r1 * K + acol] : make_float4(0, 0, 0, 0);
        rb[0] = *(const float4*)&B[(size_t)brow * 128 + bcol];
        rb[1] = *(const float4*)&B[(size_t)(brow + 8) * 128 + bcol];
    }
    {
        uint32_t* pa0 = &As[0][arow][acol];
        pa0[0] = f2tf32(ra[0].x); pa0[1] = f2tf32(ra[0].y); pa0[2] = f2tf32(ra[0].z); pa0[3] = f2tf32(ra[0].w);
        uint32_t* pa1 = &As[0][arow + 64][acol];
        pa1[0] = f2tf32(ra[1].x); pa1[1] = f2tf32(ra[1].y); pa1[2] = f2tf32(ra[1].z); pa1[3] = f2tf32(ra[1].w);
        uint32_t* pb0 = &Bs[0][brow][bcol];
        pb0[0] = f2tf32(rb[0].x); pb0[1] = f2tf32(rb[0].y); pb0[2] = f2tf32(rb[0].z); pb0[3] = f2tf32(rb[0].w);
        uint32_t* pb1 = &Bs[0][brow + 8][bcol];
        pb1[0] = f2tf32(rb[1].x); pb1[1] = f2tf32(rb[1].y); pb1[2] = f2tf32(rb[1].z); pb1[3] = f2tf32(rb[1].w);
    }
    __syncthreads();

    for (int c0 = 0; c0 < nch; c0++) {
        int cur = c0 & 1;
        if (c0 + 1 < nch) {
            int k0 = (c0 + 1) * BKQ;
            int r0 = m0 + arow, r1 = m0 + arow + 64;
            ra[0] = (r0 < M) ? *(const float4*)&A[(size_t)r0 * K + k0 + acol] : make_float4(0, 0, 0, 0);
            ra[1] = (r1 < M) ? *(const float4*)&A[(size_t)r1 * K + k0 + acol] : make_float4(0, 0, 0, 0);
            rb[0] = *(const float4*)&B[(size_t)(k0 + brow) * 128 + bcol];
            rb[1] = *(const float4*)&B[(size_t)(k0 + brow + 8) * 128 + bcol];
        }
#pragma unroll
        for (int ks = 0; ks < 2; ks++) {
            int kb = ks * 8;
            uint32_t af[4][4], bf[4][2];
#pragma unroll
            for (int mt = 0; mt < 4; mt++) {
                int row = wm * 64 + mt * 16 + g;
                af[mt][0] = As[cur][row][kb + kk];
                af[mt][1] = As[cur][row + 8][kb + kk];
                af[mt][2] = As[cur][row][kb + kk + 4];
                af[mt][3] = As[cur][row + 8][kb + kk + 4];
            }
#pragma unroll
            for (int nt = 0; nt < 4; nt++) {
                int col = wn * 32 + nt * 8 + g;
                bf[nt][0] = Bs[cur][kb + kk][col];
                bf[nt][1] = Bs[cur][kb + kk + 4][col];
            }
#pragma unroll
            for (int mt = 0; mt < 4; mt++)
#pragma unroll
                for (int nt = 0; nt < 4; nt++)
                    mma_tf32(c[mt][nt], af[mt], bf[nt]);
        }
        if (c0 + 1 < nch) {
            int nb = (c0 + 1) & 1;
            uint32_t* pa0 = &As[nb][arow][acol];
            pa0[0] = f2tf32(ra[0].x); pa0[1] = f2tf32(ra[0].y); pa0[2] = f2tf32(ra[0].z); pa0[3] = f2tf32(ra[0].w);
            uint32_t* pa1 = &As[nb][arow + 64][acol];
            pa1[0] = f2tf32(ra[1].x); pa1[1] = f2tf32(ra[1].y); pa1[2] = f2tf32(ra[1].z); pa1[3] = f2tf32(ra[1].w);
            uint32_t* pb0 = &Bs[nb][brow][bcol];
            pb0[0] = f2tf32(rb[0].x); pb0[1] = f2tf32(rb[0].y); pb0[2] = f2tf32(rb[0].z); pb0[3] = f2tf32(rb[0].w);
            uint32_t* pb1 = &Bs[nb][brow + 8][bcol];
            pb1[0] = f2tf32(rb[1].x); pb1[1] = f2tf32(rb[1].y); pb1[2] = f2tf32(rb[1].z); pb1[3] = f2tf32(rb[1].w);
            __syncthreads();
        }
    }

    // epilogue: store C + fused attention-dot partials
#pragma unroll
    for (int mt = 0; mt < 4; mt++) {
        int row = m0 + wm * 64 + mt * 16 + g;
#pragma unroll
        for (int nt = 0; nt < 4; nt++) {
            int col = wn * 32 + nt * 8 + kk * 2;
            if (row < M)
                *(float2*)&C[(size_t)row * 128 + col] = make_float2(c[mt][nt][0], c[mt][nt][1]);
            if (row + 8 < M)
                *(float2*)&C[(size_t)(row + 8) * 128 + col] = make_float2(c[mt][nt][2], c[mt][nt][3]);
        }
        // attention partial dots for both rows of this mt
#pragma unroll
        for (int half = 0; half < 2; half++) {
            float ps = 0.f, pd = 0.f;
#pragma unroll
            for (int nt = 0; nt < 4; nt++) {
#pragma unroll
                for (int i = 0; i < 2; i++) {
                    int col = wn * 32 + nt * 8 + kk * 2 + i;
                    float v = c[mt][nt][half * 2 + i];
                    ps += v * s_av[0][col];
                    pd += v * s_av[1][col];
                }
            }
            ps += __shfl_xor_sync(0xFFFFFFFF, ps, 1);
            ps += __shfl_xor_sync(0xFFFFFFFF, ps, 2);
            pd += __shfl_xor_sync(0xFFFFFFFF, pd, 1);
            pd += __shfl_xor_sync(0xFFFFFFFF, pd, 2);
            if (kk == 0) {
                int lr = wm * 64 + mt * 16 + g + half * 8;
                atomicAdd(&s_pa[lr][0], ps);
                atomicAdd(&s_pa[lr][1], pd);
            }
        }
    }
    __syncthreads();
    if (tid < 128 && m0 + tid < M) {
        g_as[m0 + tid] = s_pa[tid][0];
        g_ad[m0 + tid] = s_pa[tid][1];
    }
}

__device__ __forceinline__ float lrelu(float x) {
    return x > 0.f ? x : NEG_SLOPE * x;
}

// ---------------- gather-side softmax aggregation (2 passes, chunked shfl) -----
__global__ __launch_bounds__(256) void k_aggregate(const float* __restrict__ h,
                                                   const float* __restrict__ b,
                                                   float* __restrict__ out) {
    int v = (blockIdx.x * blockDim.x + threadIdx.x) >> 5;
    int lane = threadIdx.x & 31;
    if (v >= NN) return;
    int beg = g_rowptr[v];
    int end = g_rowptr[v + 1];
    float adv = g_ad[v];

    // pass 1: max
    float m = -1e30f;
    for (int j = beg + lane; j < end; j += 32)
        m = fmaxf(m, lrelu(__ldg(&g_as[g_csr_src[j]]) + adv));
#pragma unroll
    for (int off = 16; off > 0; off >>= 1)
        m = fmaxf(m, __shfl_xor_sync(0xFFFFFFFF, m, off));

    // pass 2: weights + denominator + feature accumulate, 32-edge chunks
    float4 acc = make_float4(0.f, 0.f, 0.f, 0.f);
    float den_p = 0.f;
    for (int c0 = beg; c0 < end; c0 += 32) {
        int n = min(32, end - c0);
        int s = 0;
        float w = 0.f;
        if (lane < n) {
            s = g_csr_src[c0 + lane];
            w = __expf(lrelu(__ldg(&g_as[s]) + adv) - m);
        }
        den_p += w;
        for (int j = 0; j < n; j++) {
            float wb = __shfl_sync(0xFFFFFFFF, w, j);
            int sb = __shfl_sync(0xFFFFFFFF, s, j);
            float4 hv = *(const float4*)&h[(size_t)sb * 128 + lane * 4];
            acc.x += wb * hv.x;
            acc.y += wb * hv.y;
            acc.z += wb * hv.z;
            acc.w += wb * hv.w;
        }
    }
#pragma unroll
    for (int off = 16; off > 0; off >>= 1)
        den_p += __shfl_xor_sync(0xFFFFFFFF, den_p, off);

    float inv = 1.f / den_p;
    float4 b4 = *(const float4*)&b[lane * 4];
    float4 o = make_float4(acc.x * inv + b4.x, acc.y * inv + b4.y,
                           acc.z * inv + b4.z, acc.w * inv + b4.w);
    *(float4*)&out[(size_t)v * 128 + lane * 4] = o;
}

// ---------------- pooling ------------------------------------------------------
__device__ __forceinline__ int lower_bound_i(const int* a, int n, int key) {
    int lo = 0, hi = n;
    while (lo < hi) {
        int mid = (lo + hi) >> 1;
        if (a[mid] < key) lo = mid + 1;
        else hi = mid;
    }
    return lo;
}

__global__ __launch_bounds__(128) void k_pool(const float* __restrict__ x,
                                              const int* __restrict__ batch) {
    int g = blockIdx.x;
    int f = threadIdx.x;
    __shared__ int s_lo, s_hi;
    if (f == 0) s_lo = lower_bound_i(batch, NN, g);
    if (f == 1) s_hi = lower_bound_i(batch, NN, g + 1);
    __syncthreads();
    int lo = s_lo, hi = s_hi;
    float s = 0.f, mx = -1e30f;
    for (int i = lo; i < hi; i++) {
        float v = x[(size_t)i * 128 + f];
        s += v;
        mx = fmaxf(mx, v);
    }
    int cnt = hi - lo;
    g_mean[g * 128 + f] = s / (float)max(cnt, 1);
    g_max[g * 128 + f] = (cnt > 0) ? mx : 0.f;
}

// ---------------- fold g-feature path ------------------------------------------
__global__ void k_fold(const float* __restrict__ Wg, const float* __restrict__ bg,
                       const float* __restrict__ Wo, const float* __restrict__ bo) {
    int t = threadIdx.x;
    if (t < GF * 2) {
        int k = t >> 1, c = t & 1;
        float s = 0.f;
        for (int j = 0; j < EMB; j++)
            s += Wg[k * EMB + j] * Wo[(256 + j) * 2 + c];
        g_wgo[t] = s;
    } else if (t < GF * 2 + 2) {
        int c = t - GF * 2;
        float s = bo[c];
        for (int j = 0; j < EMB; j++)
            s += bg[j] * Wo[(256 + j) * 2 + c];
        g_bgo[c] = s;
    }
}

// ---------------- head ---------------------------------------------------------
__global__ __launch_bounds__(256) void k_head(const float* __restrict__ gfeat,
                                              const float* __restrict__ Wo,
                                              float* __restrict__ out) {
    int g = (blockIdx.x * blockDim.x + threadIdx.x) >> 5;
    int lane = threadIdx.x & 31;
    if (g >= GG) return;
    float s0 = 0.f, s1 = 0.f;
#pragma unroll
    for (int j = lane; j < 128; j += 32) {
        float mn = g_mean[g * 128 + j];
        float mx = g_max[g * 128 + j];
        s0 += mn * Wo[j * 2 + 0] + mx * Wo[(128 + j) * 2 + 0];
        s1 += mn * Wo[j * 2 + 1] + mx * Wo[(128 + j) * 2 + 1];
    }
    float gv = gfeat[g * GF + lane];
    s0 += gv * g_wgo[lane * 2 + 0];
    s1 += gv * g_wgo[lane * 2 + 1];
#pragma unroll
    for (int off = 16; off > 0; off >>= 1) {
        s0 += __shfl_xor_sync(0xFFFFFFFF, s0, off);
        s1 += __shfl_xor_sync(0xFFFFFFFF, s1, off);
    }
    if (lane == 0) {
        float l0 = s0 + g_bgo[0];
        float l1 = s1 + g_bgo[1];
        float m = fmaxf(l0, l1);
        float lse = m + logf(expf(l0 - m) + expf(l1 - m));
        out[g * 2 + 0] = l0 - lse;
        out[g * 2 + 1] = l1 - lse;
    }
}

// ---------------- launch --------------------------------------------------------
extern "C" void kernel_launch(void* const* d_in, const int* in_sizes, int n_in,
                              void* d_out, int out_size) {
    const float* x      = (const float*)d_in[0];
    const int*   edges  = (const int*)d_in[1];     // [2, E]
    const int*   batch  = (const int*)d_in[2];
    const float* gfeat  = (const float*)d_in[3];
    const float* W1     = (const float*)d_in[4];
    const float* a1s    = (const float*)d_in[5];
    const float* a1d    = (const float*)d_in[6];
    const float* b1     = (const float*)d_in[7];
    const float* W2     = (const float*)d_in[8];
    const float* a2s    = (const float*)d_in[9];
    const float* a2d    = (const float*)d_in[10];
    const float* b2     = (const float*)d_in[11];
    const float* Wg     = (const float*)d_in[12];
    const float* bg     = (const float*)d_in[13];
    const float* Wo     = (const float*)d_in[14];
    const float* bo     = (const float*)d_in[15];
    float* out = (float*)d_out;

    const int* src = edges;
    const int* dst = edges + EE;

    float* d_h;  cudaGetSymbolAddress((void**)&d_h,  g_h);
    float* d_x2; cudaGetSymbolAddress((void**)&d_x2, g_x2);

    // CSR build (4 launches, all plain kernels)
    k_zero<<<(NN + 255) / 256, 256>>>();
    k_hist<<<(EE + 255) / 256, 256>>>(dst);
    k_scan<<<1, 1024>>>();
    k_fill<<<(NN + EE + 255) / 256, 256>>>(src, dst);

    int gemm_blocks = (NN + BM - 1) / BM;
    int warp_blocks = (NN * 32 + 255) / 256;

    // layer 1 (GEMM computes h, as, ad)
    k_gemm_tc<<<gemm_blocks, 256>>>(x, W1, d_h, a1s, a1d, NN, FIN);
    k_aggregate<<<warp_blocks, 256>>>(d_h, b1, d_x2);

    // layer 2
    k_gemm_tc<<<gemm_blocks, 256>>>(d_x2, W2, d_h, a2s, a2d, NN, EMB);
    k_aggregate<<<warp_blocks, 256>>>(d_h, b2, d_x2);

    // pooling + head
    k_pool<<<GG, 128>>>(d_x2, batch);
    k_fold<<<1, 96>>>(Wg, bg, Wo, bo);
    k_head<<<(GG * 32 + 255) / 256, 256>>>(gfeat, Wo, out);
}

// round 7
// speedup vs baseline: 1.6210x; 1.0595x over previous
#include <cuda_runtime.h>
#include <cuda_bf16.h>
#include <cstdint>

#define NN 50000
#define EE 800000
#define FIN 256
#define EMB 128
#define GF 32
#define GG 256
#define NEG_SLOPE 0.2f
#define ETOT (EE + NN)
#define SCAN_B 1024
#define NBLK ((NN + SCAN_B - 1) / SCAN_B)   // 49

// ---------------- scratch (device globals; no allocations allowed) -------------
__device__ float g_h[(size_t)NN * EMB];
__device__ float g_x2[(size_t)NN * EMB];
__device__ float g_as[NN];
__device__ float g_ad[NN];
__device__ int   g_counts[NN];
__device__ int   g_rowptr[NN + 1];
__device__ int   g_bsum[NBLK];
__device__ int   g_csr_src[ETOT];
__device__ float g_mean[GG * EMB];
__device__ float g_max[GG * EMB];
__device__ float g_wgo[GF * 2];
__device__ float g_bgo[2];

// ---------------- CSR build ----------------------------------------------------
__global__ void k_zero() {
    int i = blockIdx.x * blockDim.x + threadIdx.x;
    if (i < NN) g_counts[i] = 0;
}

__global__ void k_hist(const int* __restrict__ dst) {
    int e = blockIdx.x * blockDim.x + threadIdx.x;
    if (e < EE) atomicAdd(&g_counts[dst[e]], 1);
}

// local scan: each block scans 1024 (counts+1) values, writes local-exclusive
// prefix into rowptr and block total into g_bsum
__global__ __launch_bounds__(SCAN_B) void k_scan1() {
    __shared__ int warp_sums[32];
    int t = threadIdx.x;
    int lane = t & 31, w = t >> 5;
    int i = blockIdx.x * SCAN_B + t;
    int v = (i < NN) ? (g_counts[i] + 1) : 0;
    int x = v;
#pragma unroll
    for (int off = 1; off < 32; off <<= 1) {
        int y = __shfl_up_sync(0xFFFFFFFF, x, off);
        if (lane >= off) x += y;
    }
    if (lane == 31) warp_sums[w] = x;
    __syncthreads();
    if (w == 0) {
        int s = warp_sums[lane];
#pragma unroll
        for (int off = 1; off < 32; off <<= 1) {
            int y = __shfl_up_sync(0xFFFFFFFF, s, off);
            if (lane >= off) s += y;
        }
        warp_sums[lane] = s;
    }
    __syncthreads();
    if (i < NN) g_rowptr[i] = (w > 0 ? warp_sums[w - 1] : 0) + x - v;
    if (t == SCAN_B - 1) g_bsum[blockIdx.x] = warp_sums[31];
}

// scan the 49 block sums (exclusive)
__global__ void k_scan2() {
    int t = threadIdx.x;   // 64 threads
    __shared__ int sh[64];
    int v = (t < NBLK) ? g_bsum[t] : 0;
    sh[t] = v;
    __syncthreads();
    if (t == 0) {
        int run = 0;
        for (int j = 0; j < NBLK; j++) {
            int tmp = sh[j];
            sh[j] = run;
            run += tmp;
        }
    }
    __syncthreads();
    if (t < NBLK) g_bsum[t] = sh[t];
}

// fixup: final rowptr, scatter cursors; rowptr[NN] = ETOT (constant)
__global__ void k_scan3() {
    int i = blockIdx.x * blockDim.x + threadIdx.x;
    if (i < NN) {
        int r = g_rowptr[i] + g_bsum[i >> 10];
        g_rowptr[i] = r;
        g_counts[i] = r + 1;      // cursor past the self-loop slot
    }
    if (i == 0) g_rowptr[NN] = ETOT;
}

// self-loop fill + edge scatter (disjoint slots)
__global__ void k_fill(const int* __restrict__ src, const int* __restrict__ dst) {
    int t = blockIdx.x * blockDim.x + threadIdx.x;
    if (t < NN) {
        g_csr_src[g_rowptr[t]] = t;
    } else if (t < NN + EE) {
        int e = t - NN;
        int d = dst[e];
        int pos = atomicAdd(&g_counts[d], 1);
        g_csr_src[pos] = src[e];
    }
}

// ---------------- tf32 tensor-core GEMM + fused attention dots -----------------
__device__ __forceinline__ uint32_t f2tf32(float x) {
    uint32_t r;
    asm("cvt.rna.tf32.f32 %0, %1;" : "=r"(r) : "f"(x));
    return r;
}

__device__ __forceinline__ void mma_tf32(float* c, const uint32_t* a, const uint32_t* b) {
    asm volatile(
        "mma.sync.aligned.m16n8k8.row.col.f32.tf32.tf32.f32 "
        "{%0,%1,%2,%3}, {%4,%5,%6,%7}, {%8,%9}, {%0,%1,%2,%3};\n"
        : "+f"(c[0]), "+f"(c[1]), "+f"(c[2]), "+f"(c[3])
        : "r"(a[0]), "r"(a[1]), "r"(a[2]), "r"(a[3]), "r"(b[0]), "r"(b[1]));
}

#define BM 128
#define BKQ 16
#define AP 20
#define BP 132

__global__ __launch_bounds__(256) void k_gemm_tc(const float* __restrict__ A,
                                                 const float* __restrict__ B,
                                                 float* __restrict__ C,
                                                 const float* __restrict__ a_src,
                                                 const float* __restrict__ a_dst,
                                                 int M, int K) {
    __shared__ uint32_t As[2][BM][AP];
    __shared__ uint32_t Bs[2][BKQ][BP];
    __shared__ float s_av[2][128];
    __shared__ float s_pa[128][2];
    int tid = threadIdx.x;
    int lane = tid & 31, wid = tid >> 5;
    int wm = wid >> 2;
    int wn = wid & 3;
    int g = lane >> 2, kk = lane & 3;
    int m0 = blockIdx.x * BM;

    if (tid < 128) {
        s_av[0][tid] = a_src[tid];
        s_pa[tid][0] = 0.f;
        s_pa[tid][1] = 0.f;
    } else {
        s_av[1][tid - 128] = a_dst[tid - 128];
    }

    int arow = tid >> 2;
    int acol = (tid & 3) << 2;
    int brow = tid >> 5;
    int bcol = (tid & 31) << 2;

    float c[4][4][4];
#pragma unroll
    for (int mt = 0; mt < 4; mt++)
#pragma unroll
        for (int nt = 0; nt < 4; nt++)
#pragma unroll
            for (int i = 0; i < 4; i++) c[mt][nt][i] = 0.f;

    float4 ra[2], rb[2];
    const int nch = K / BKQ;

    {
        int r0 = m0 + arow, r1 = m0 + arow + 64;
        ra[0] = (r0 < M) ? *(const float4*)&A[(size_t)r0 * K + acol] : make_float4(0, 0, 0, 0);
        ra[1] = (r1 < M) ? *(const float4*)&A[(size_t)r1 * K + acol] : make_float4(0, 0, 0, 0);
        rb[0] = *(const float4*)&B[(size_t)brow * 128 + bcol];
        rb[1] = *(const float4*)&B[(size_t)(brow + 8) * 128 + bcol];
    }
    {
        uint32_t* pa0 = &As[0][arow][acol];
        pa0[0] = f2tf32(ra[0].x); pa0[1] = f2tf32(ra[0].y); pa0[2] = f2tf32(ra[0].z); pa0[3] = f2tf32(ra[0].w);
        uint32_t* pa1 = &As[0][arow + 64][acol];
        pa1[0] = f2tf32(ra[1].x); pa1[1] = f2tf32(ra[1].y); pa1[2] = f2tf32(ra[1].z); pa1[3] = f2tf32(ra[1].w);
        uint32_t* pb0 = &Bs[0][brow][bcol];
        pb0[0] = f2tf32(rb[0].x); pb0[1] = f2tf32(rb[0].y); pb0[2] = f2tf32(rb[0].z); pb0[3] = f2tf32(rb[0].w);
        uint32_t* pb1 = &Bs[0][brow + 8][bcol];
        pb1[0] = f2tf32(rb[1].x); pb1[1] = f2tf32(rb[1].y); pb1[2] = f2tf32(rb[1].z); pb1[3] = f2tf32(rb[1].w);
    }
    __syncthreads();

    for (int c0 = 0; c0 < nch; c0++) {
        int cur = c0 & 1;
        if (c0 + 1 < nch) {
            int k0 = (c0 + 1) * BKQ;
            int r0 = m0 + arow, r1 = m0 + arow + 64;
            ra[0] = (r0 < M) ? *(const float4*)&A[(size_t)r0 * K + k0 + acol] : make_float4(0, 0, 0, 0);
            ra[1] = (r1 < M) ? *(const float4*)&A[(size_t)r1 * K + k0 + acol] : make_float4(0, 0, 0, 0);
            rb[0] = *(const float4*)&B[(size_t)(k0 + brow) * 128 + bcol];
            rb[1] = *(const float4*)&B[(size_t)(k0 + brow + 8) * 128 + bcol];
        }
#pragma unroll
        for (int ks = 0; ks < 2; ks++) {
            int kb = ks * 8;
            uint32_t af[4][4], bf[4][2];
#pragma unroll
            for (int mt = 0; mt < 4; mt++) {
                int row = wm * 64 + mt * 16 + g;
                af[mt][0] = As[cur][row][kb + kk];
                af[mt][1] = As[cur][row + 8][kb + kk];
                af[mt][2] = As[cur][row][kb + kk + 4];
                af[mt][3] = As[cur][row + 8][kb + kk + 4];
            }
#pragma unroll
            for (int nt = 0; nt < 4; nt++) {
                int col = wn * 32 + nt * 8 + g;
                bf[nt][0] = Bs[cur][kb + kk][col];
                bf[nt][1] = Bs[cur][kb + kk + 4][col];
            }
#pragma unroll
            for (int mt = 0; mt < 4; mt++)
#pragma unroll
                for (int nt = 0; nt < 4; nt++)
                    mma_tf32(c[mt][nt], af[mt], bf[nt]);
        }
        if (c0 + 1 < nch) {
            int nb = (c0 + 1) & 1;
            uint32_t* pa0 = &As[nb][arow][acol];
            pa0[0] = f2tf32(ra[0].x); pa0[1] = f2tf32(ra[0].y); pa0[2] = f2tf32(ra[0].z); pa0[3] = f2tf32(ra[0].w);
            uint32_t* pa1 = &As[nb][arow + 64][acol];
            pa1[0] = f2tf32(ra[1].x); pa1[1] = f2tf32(ra[1].y); pa1[2] = f2tf32(ra[1].z); pa1[3] = f2tf32(ra[1].w);
            uint32_t* pb0 = &Bs[nb][brow][bcol];
            pb0[0] = f2tf32(rb[0].x); pb0[1] = f2tf32(rb[0].y); pb0[2] = f2tf32(rb[0].z); pb0[3] = f2tf32(rb[0].w);
            uint32_t* pb1 = &Bs[nb][brow + 8][bcol];
            pb1[0] = f2tf32(rb[1].x); pb1[1] = f2tf32(rb[1].y); pb1[2] = f2tf32(rb[1].z); pb1[3] = f2tf32(rb[1].w);
            __syncthreads();
        }
    }

#pragma unroll
    for (int mt = 0; mt < 4; mt++) {
        int row = m0 + wm * 64 + mt * 16 + g;
#pragma unroll
        for (int nt = 0; nt < 4; nt++) {
            int col = wn * 32 + nt * 8 + kk * 2;
            if (row < M)
                *(float2*)&C[(size_t)row * 128 + col] = make_float2(c[mt][nt][0], c[mt][nt][1]);
            if (row + 8 < M)
                *(float2*)&C[(size_t)(row + 8) * 128 + col] = make_float2(c[mt][nt][2], c[mt][nt][3]);
        }
#pragma unroll
        for (int half = 0; half < 2; half++) {
            float ps = 0.f, pd = 0.f;
#pragma unroll
            for (int nt = 0; nt < 4; nt++) {
#pragma unroll
                for (int i = 0; i < 2; i++) {
                    int col = wn * 32 + nt * 8 + kk * 2 + i;
                    float v = c[mt][nt][half * 2 + i];
                    ps += v * s_av[0][col];
                    pd += v * s_av[1][col];
                }
            }
            ps += __shfl_xor_sync(0xFFFFFFFF, ps, 1);
            ps += __shfl_xor_sync(0xFFFFFFFF, ps, 2);
            pd += __shfl_xor_sync(0xFFFFFFFF, pd, 1);
            pd += __shfl_xor_sync(0xFFFFFFFF, pd, 2);
            if (kk == 0) {
                int lr = wm * 64 + mt * 16 + g + half * 8;
                atomicAdd(&s_pa[lr][0], ps);
                atomicAdd(&s_pa[lr][1], pd);
            }
        }
    }
    __syncthreads();
    if (tid < 128 && m0 + tid < M) {
        g_as[m0 + tid] = s_pa[tid][0];
        g_ad[m0 + tid] = s_pa[tid][1];
    }
}

__device__ __forceinline__ float lrelu(float x) {
    return x > 0.f ? x : NEG_SLOPE * x;
}

// ---------------- single-pass aggregation (no max: softmax shift-invariant, ----
// logits bounded ~|10| << 88, exp cannot overflow) ------------------------------
__global__ __launch_bounds__(256) void k_aggregate(const float* __restrict__ h,
                                                   const float* __restrict__ b,
                                                   float* __restrict__ out) {
    int v = (blockIdx.x * blockDim.x + threadIdx.x) >> 5;
    int lane = threadIdx.x & 31;
    if (v >= NN) return;
    int beg = g_rowptr[v];
    int end = g_rowptr[v + 1];
    float adv = g_ad[v];

    float4 acc = make_float4(0.f, 0.f, 0.f, 0.f);
    float den_p = 0.f;
    for (int c0 = beg; c0 < end; c0 += 32) {
        int n = min(32, end - c0);
        int s = 0;
        float w = 0.f;
        if (lane < n) {
            s = g_csr_src[c0 + lane];
            w = __expf(lrelu(__ldg(&g_as[s]) + adv));
        }
        den_p += w;
        for (int j = 0; j < n; j++) {
            float wb = __shfl_sync(0xFFFFFFFF, w, j);
            int sb = __shfl_sync(0xFFFFFFFF, s, j);
            float4 hv = *(const float4*)&h[(size_t)sb * 128 + lane * 4];
            acc.x += wb * hv.x;
            acc.y += wb * hv.y;
            acc.z += wb * hv.z;
            acc.w += wb * hv.w;
        }
    }
#pragma unroll
    for (int off = 16; off > 0; off >>= 1)
        den_p += __shfl_xor_sync(0xFFFFFFFF, den_p, off);

    float inv = 1.f / den_p;
    float4 b4 = *(const float4*)&b[lane * 4];
    float4 o = make_float4(acc.x * inv + b4.x, acc.y * inv + b4.y,
                           acc.z * inv + b4.z, acc.w * inv + b4.w);
    *(float4*)&out[(size_t)v * 128 + lane * 4] = o;
}

// ---------------- pooling + fold (block 0) -------------------------------------
__device__ __forceinline__ int lower_bound_i(const int* a, int n, int key) {
    int lo = 0, hi = n;
    while (lo < hi) {
        int mid = (lo + hi) >> 1;
        if (a[mid] < key) lo = mid + 1;
        else hi = mid;
    }
    return lo;
}

__global__ __launch_bounds__(128) void k_pool(const float* __restrict__ x,
                                              const int* __restrict__ batch,
                                              const float* __restrict__ Wg,
                                              const float* __restrict__ bg,
                                              const float* __restrict__ Wo,
                                              const float* __restrict__ bo) {
    int g = blockIdx.x;
    int f = threadIdx.x;
    __shared__ int s_lo, s_hi;
    if (f == 0) s_lo = lower_bound_i(batch, NN, g);
    if (f == 1) s_hi = lower_bound_i(batch, NN, g + 1);
    __syncthreads();
    int lo = s_lo, hi = s_hi;
    float s = 0.f, mx = -1e30f;
    for (int i = lo; i < hi; i++) {
        float v = x[(size_t)i * 128 + f];
        s += v;
        mx = fmaxf(mx, v);
    }
    int cnt = hi - lo;
    g_mean[g * 128 + f] = s / (float)max(cnt, 1);
    g_max[g * 128 + f] = (cnt > 0) ? mx : 0.f;

    // fold g-feature path (block 0 only): wgo = Wg @ Wo[256:384], bgo = bg@.. + bo
    if (g == 0) {
        int t = f;
        if (t < GF * 2) {
            int k = t >> 1, c = t & 1;
            float acc = 0.f;
            for (int j = 0; j < EMB; j++)
                acc += Wg[k * EMB + j] * Wo[(256 + j) * 2 + c];
            g_wgo[t] = acc;
        } else if (t < GF * 2 + 2) {
            int c = t - GF * 2;
            float acc = bo[c];
            for (int j = 0; j < EMB; j++)
                acc += bg[j] * Wo[(256 + j) * 2 + c];
            g_bgo[c] = acc;
        }
    }
}

// ---------------- head ---------------------------------------------------------
__global__ __launch_bounds__(256) void k_head(const float* __restrict__ gfeat,
                                              const float* __restrict__ Wo,
                                              float* __restrict__ out) {
    int g = (blockIdx.x * blockDim.x + threadIdx.x) >> 5;
    int lane = threadIdx.x & 31;
    if (g >= GG) return;
    float s0 = 0.f, s1 = 0.f;
#pragma unroll
    for (int j = lane; j < 128; j += 32) {
        float mn = g_mean[g * 128 + j];
        float mx = g_max[g * 128 + j];
        s0 += mn * Wo[j * 2 + 0] + mx * Wo[(128 + j) * 2 + 0];
        s1 += mn * Wo[j * 2 + 1] + mx * Wo[(128 + j) * 2 + 1];
    }
    float gv = gfeat[g * GF + lane];
    s0 += gv * g_wgo[lane * 2 + 0];
    s1 += gv * g_wgo[lane * 2 + 1];
#pragma unroll
    for (int off = 16; off > 0; off >>= 1) {
        s0 += __shfl_xor_sync(0xFFFFFFFF, s0, off);
        s1 += __shfl_xor_sync(0xFFFFFFFF, s1, off);
    }
    if (lane == 0) {
        float l0 = s0 + g_bgo[0];
        float l1 = s1 + g_bgo[1];
        float m = fmaxf(l0, l1);
        float lse = m + logf(expf(l0 - m) + expf(l1 - m));
        out[g * 2 + 0] = l0 - lse;
        out[g * 2 + 1] = l1 - lse;
    }
}

// ---------------- launch --------------------------------------------------------
extern "C" void kernel_launch(void* const* d_in, const int* in_sizes, int n_in,
                              void* d_out, int out_size) {
    const float* x      = (const float*)d_in[0];
    const int*   edges  = (const int*)d_in[1];
    const int*   batch  = (const int*)d_in[2];
    const float* gfeat  = (const float*)d_in[3];
    const float* W1     = (const float*)d_in[4];
    const float* a1s    = (const float*)d_in[5];
    const float* a1d    = (const float*)d_in[6];
    const float* b1     = (const float*)d_in[7];
    const float* W2     = (const float*)d_in[8];
    const float* a2s    = (const float*)d_in[9];
    const float* a2d    = (const float*)d_in[10];
    const float* b2     = (const float*)d_in[11];
    const float* Wg     = (const float*)d_in[12];
    const float* bg     = (const float*)d_in[13];
    const float* Wo     = (const float*)d_in[14];
    const float* bo     = (const float*)d_in[15];
    float* out = (float*)d_out;

    const int* src = edges;
    const int* dst = edges + EE;

    float* d_h;  cudaGetSymbolAddress((void**)&d_h,  g_h);
    float* d_x2; cudaGetSymbolAddress((void**)&d_x2, g_x2);

    // CSR build (stateless: explicit zero each call)
    k_zero<<<(NN + 255) / 256, 256>>>();
    k_hist<<<(EE + 255) / 256, 256>>>(dst);
    k_scan1<<<NBLK, SCAN_B>>>();
    k_scan2<<<1, 64>>>();
    k_scan3<<<(NN + 255) / 256, 256>>>();
    k_fill<<<(NN + EE + 255) / 256, 256>>>(src, dst);

    int gemm_blocks = (NN + BM - 1) / BM;
    int warp_blocks = (NN * 32 + 255) / 256;

    // layer 1 (GEMM computes h, as, ad)
    k_gemm_tc<<<gemm_blocks, 256>>>(x, W1, d_h, a1s, a1d, NN, FIN);
    k_aggregate<<<warp_blocks, 256>>>(d_h, b1, d_x2);

    // layer 2
    k_gemm_tc<<<gemm_blocks, 256>>>(d_x2, W2, d_h, a2s, a2d, NN, EMB);
    k_aggregate<<<warp_blocks, 256>>>(d_h, b2, d_x2);

    // pooling (+ fold) + head
    k_pool<<<GG, 128>>>(d_x2, batch, Wg, bg, Wo, bo);
    k_head<<<(GG * 32 + 255) / 256, 256>>>(gfeat, Wo, out);
}

// round 8
// speedup vs baseline: 1.7166x; 1.0590x over previous
#include <cuda_runtime.h>
#include <cuda_bf16.h>
#include <cstdint>

#define NN 50000
#define EE 800000
#define FIN 256
#define EMB 128
#define GF 32
#define GG 256
#define NEG_SLOPE 0.2f
#define ETOT (EE + NN)
#define SCAN_B 1024
#define NBLK ((NN + SCAN_B - 1) / SCAN_B)   // 49

// ---------------- scratch (device globals; no allocations allowed) -------------
__device__ __nv_bfloat16 g_hb[(size_t)NN * EMB];   // h in bf16 (gather payload)
__device__ float g_x2[(size_t)NN * EMB];           // layer output (fp32)
__device__ float g_as[NN];
__device__ float g_ad[NN];
__device__ int   g_counts[NN];
__device__ int   g_rowptr[NN + 1];
__device__ int   g_bsum[NBLK];
__device__ int   g_csr_src[ETOT];
__device__ float g_mean[GG * EMB];
__device__ float g_max[GG * EMB];
__device__ float g_wgo[GF * 2];
__device__ float g_bgo[2];

// ---------------- CSR build ----------------------------------------------------
__global__ void k_zero() {
    int i = blockIdx.x * blockDim.x + threadIdx.x;
    if (i < NN) g_counts[i] = 0;
}

__global__ void k_hist(const int* __restrict__ dst) {
    int e = blockIdx.x * blockDim.x + threadIdx.x;
    if (e < EE) atomicAdd(&g_counts[dst[e]], 1);
}

// local scan: each block scans 1024 (counts+1) values, writes local-exclusive
// prefix into rowptr and block total into g_bsum
__global__ __launch_bounds__(SCAN_B) void k_scan1() {
    __shared__ int warp_sums[32];
    int t = threadIdx.x;
    int lane = t & 31, w = t >> 5;
    int i = blockIdx.x * SCAN_B + t;
    int v = (i < NN) ? (g_counts[i] + 1) : 0;
    int x = v;
#pragma unroll
    for (int off = 1; off < 32; off <<= 1) {
        int y = __shfl_up_sync(0xFFFFFFFF, x, off);
        if (lane >= off) x += y;
    }
    if (lane == 31) warp_sums[w] = x;
    __syncthreads();
    if (w == 0) {
        int s = warp_sums[lane];
#pragma unroll
        for (int off = 1; off < 32; off <<= 1) {
            int y = __shfl_up_sync(0xFFFFFFFF, s, off);
            if (lane >= off) s += y;
        }
        warp_sums[lane] = s;
    }
    __syncthreads();
    if (i < NN) g_rowptr[i] = (w > 0 ? warp_sums[w - 1] : 0) + x - v;
    if (t == SCAN_B - 1) g_bsum[blockIdx.x] = warp_sums[31];
}

// fixup: every block redundantly scans the 49 block sums, then applies.
// also writes scatter cursors; rowptr[NN] = ETOT (constant)
__global__ __launch_bounds__(256) void k_scan3() {
    __shared__ int sh[NBLK];
    int t = threadIdx.x;
    if (t < NBLK) sh[t] = g_bsum[t];
    __syncthreads();
    if (t == 0) {
        int run = 0;
#pragma unroll
        for (int j = 0; j < NBLK; j++) {
            int tmp = sh[j];
            sh[j] = run;
            run += tmp;
        }
    }
    __syncthreads();
    int i = blockIdx.x * blockDim.x + t;
    if (i < NN) {
        int r = g_rowptr[i] + sh[i >> 10];
        g_rowptr[i] = r;
        g_counts[i] = r + 1;      // cursor past the self-loop slot
    }
    if (i == 0) g_rowptr[NN] = ETOT;
}

// self-loop fill + edge scatter (disjoint slots)
__global__ void k_fill(const int* __restrict__ src, const int* __restrict__ dst) {
    int t = blockIdx.x * blockDim.x + threadIdx.x;
    if (t < NN) {
        g_csr_src[g_rowptr[t]] = t;
    } else if (t < NN + EE) {
        int e = t - NN;
        int d = dst[e];
        int pos = atomicAdd(&g_counts[d], 1);
        g_csr_src[pos] = src[e];
    }
}

// ---------------- tf32 tensor-core GEMM + fused attention dots -----------------
// C is written in bf16 (only consumer is the aggregation gather)
__device__ __forceinline__ uint32_t f2tf32(float x) {
    uint32_t r;
    asm("cvt.rna.tf32.f32 %0, %1;" : "=r"(r) : "f"(x));
    return r;
}

__device__ __forceinline__ void mma_tf32(float* c, const uint32_t* a, const uint32_t* b) {
    asm volatile(
        "mma.sync.aligned.m16n8k8.row.col.f32.tf32.tf32.f32 "
        "{%0,%1,%2,%3}, {%4,%5,%6,%7}, {%8,%9}, {%0,%1,%2,%3};\n"
        : "+f"(c[0]), "+f"(c[1]), "+f"(c[2]), "+f"(c[3])
        : "r"(a[0]), "r"(a[1]), "r"(a[2]), "r"(a[3]), "r"(b[0]), "r"(b[1]));
}

#define BM 128
#define BKQ 16
#define AP 20
#define BP 132

__global__ __launch_bounds__(256) void k_gemm_tc(const float* __restrict__ A,
                                                 const float* __restrict__ B,
                                                 __nv_bfloat16* __restrict__ C,
                                                 const float* __restrict__ a_src,
                                                 const float* __restrict__ a_dst,
                                                 int M, int K) {
    __shared__ uint32_t As[2][BM][AP];
    __shared__ uint32_t Bs[2][BKQ][BP];
    __shared__ float s_av[2][128];
    __shared__ float s_pa[128][2];
    int tid = threadIdx.x;
    int lane = tid & 31, wid = tid >> 5;
    int wm = wid >> 2;
    int wn = wid & 3;
    int g = lane >> 2, kk = lane & 3;
    int m0 = blockIdx.x * BM;

    if (tid < 128) {
        s_av[0][tid] = a_src[tid];
        s_pa[tid][0] = 0.f;
        s_pa[tid][1] = 0.f;
    } else {
        s_av[1][tid - 128] = a_dst[tid - 128];
    }

    int arow = tid >> 2;
    int acol = (tid & 3) << 2;
    int brow = tid >> 5;
    int bcol = (tid & 31) << 2;

    float c[4][4][4];
#pragma unroll
    for (int mt = 0; mt < 4; mt++)
#pragma unroll
        for (int nt = 0; nt < 4; nt++)
#pragma unroll
            for (int i = 0; i < 4; i++) c[mt][nt][i] = 0.f;

    float4 ra[2], rb[2];
    const int nch = K / BKQ;

    {
        int r0 = m0 + arow, r1 = m0 + arow + 64;
        ra[0] = (r0 < M) ? *(const float4*)&A[(size_t)r0 * K + acol] : make_float4(0, 0, 0, 0);
        ra[1] = (r1 < M) ? *(const float4*)&A[(size_t)r1 * K + acol] : make_float4(0, 0, 0, 0);
        rb[0] = *(const float4*)&B[(size_t)brow * 128 + bcol];
        rb[1] = *(const float4*)&B[(size_t)(brow + 8) * 128 + bcol];
    }
    {
        uint32_t* pa0 = &As[0][arow][acol];
        pa0[0] = f2tf32(ra[0].x); pa0[1] = f2tf32(ra[0].y); pa0[2] = f2tf32(ra[0].z); pa0[3] = f2tf32(ra[0].w);
        uint32_t* pa1 = &As[0][arow + 64][acol];
        pa1[0] = f2tf32(ra[1].x); pa1[1] = f2tf32(ra[1].y); pa1[2] = f2tf32(ra[1].z); pa1[3] = f2tf32(ra[1].w);
        uint32_t* pb0 = &Bs[0][brow][bcol];
        pb0[0] = f2tf32(rb[0].x); pb0[1] = f2tf32(rb[0].y); pb0[2] = f2tf32(rb[0].z); pb0[3] = f2tf32(rb[0].w);
        uint32_t* pb1 = &Bs[0][brow + 8][bcol];
        pb1[0] = f2tf32(rb[1].x); pb1[1] = f2tf32(rb[1].y); pb1[2] = f2tf32(rb[1].z); pb1[3] = f2tf32(rb[1].w);
    }
    __syncthreads();

    for (int c0 = 0; c0 < nch; c0++) {
        int cur = c0 & 1;
        if (c0 + 1 < nch) {
            int k0 = (c0 + 1) * BKQ;
            int r0 = m0 + arow, r1 = m0 + arow + 64;
            ra[0] = (r0 < M) ? *(const float4*)&A[(size_t)r0 * K + k0 + acol] : make_float4(0, 0, 0, 0);
            ra[1] = (r1 < M) ? *(const float4*)&A[(size_t)r1 * K + k0 + acol] : make_float4(0, 0, 0, 0);
            rb[0] = *(const float4*)&B[(size_t)(k0 + brow) * 128 + bcol];
            rb[1] = *(const float4*)&B[(size_t)(k0 + brow + 8) * 128 + bcol];
        }
#pragma unroll
        for (int ks = 0; ks < 2; ks++) {
            int kb = ks * 8;
            uint32_t af[4][4], bf[4][2];
#pragma unroll
            for (int mt = 0; mt < 4; mt++) {
                int row = wm * 64 + mt * 16 + g;
                af[mt][0] = As[cur][row][kb + kk];
                af[mt][1] = As[cur][row + 8][kb + kk];
                af[mt][2] = As[cur][row][kb + kk + 4];
                af[mt][3] = As[cur][row + 8][kb + kk + 4];
            }
#pragma unroll
            for (int nt = 0; nt < 4; nt++) {
                int col = wn * 32 + nt * 8 + g;
                bf[nt][0] = Bs[cur][kb + kk][col];
                bf[nt][1] = Bs[cur][kb + kk + 4][col];
            }
#pragma unroll
            for (int mt = 0; mt < 4; mt++)
#pragma unroll
                for (int nt = 0; nt < 4; nt++)
                    mma_tf32(c[mt][nt], af[mt], bf[nt]);
        }
        if (c0 + 1 < nch) {
            int nb = (c0 + 1) & 1;
            uint32_t* pa0 = &As[nb][arow][acol];
            pa0[0] = f2tf32(ra[0].x); pa0[1] = f2tf32(ra[0].y); pa0[2] = f2tf32(ra[0].z); pa0[3] = f2tf32(ra[0].w);
            uint32_t* pa1 = &As[nb][arow + 64][acol];
            pa1[0] = f2tf32(ra[1].x); pa1[1] = f2tf32(ra[1].y); pa1[2] = f2tf32(ra[1].z); pa1[3] = f2tf32(ra[1].w);
            uint32_t* pb0 = &Bs[nb][brow][bcol];
            pb0[0] = f2tf32(rb[0].x); pb0[1] = f2tf32(rb[0].y); pb0[2] = f2tf32(rb[0].z); pb0[3] = f2tf32(rb[0].w);
            uint32_t* pb1 = &Bs[nb][brow + 8][bcol];
            pb1[0] = f2tf32(rb[1].x); pb1[1] = f2tf32(rb[1].y); pb1[2] = f2tf32(rb[1].z); pb1[3] = f2tf32(rb[1].w);
            __syncthreads();
        }
    }

    // epilogue: store C (bf16) + fused attention-dot partials (fp32)
#pragma unroll
    for (int mt = 0; mt < 4; mt++) {
        int row = m0 + wm * 64 + mt * 16 + g;
#pragma unroll
        for (int nt = 0; nt < 4; nt++) {
            int col = wn * 32 + nt * 8 + kk * 2;
            if (row < M)
                *(__nv_bfloat162*)&C[(size_t)row * 128 + col] =
                    __floats2bfloat162_rn(c[mt][nt][0], c[mt][nt][1]);
            if (row + 8 < M)
                *(__nv_bfloat162*)&C[(size_t)(row + 8) * 128 + col] =
                    __floats2bfloat162_rn(c[mt][nt][2], c[mt][nt][3]);
        }
#pragma unroll
        for (int half = 0; half < 2; half++) {
            float ps = 0.f, pd = 0.f;
#pragma unroll
            for (int nt = 0; nt < 4; nt++) {
#pragma unroll
                for (int i = 0; i < 2; i++) {
                    int col = wn * 32 + nt * 8 + kk * 2 + i;
                    float v = c[mt][nt][half * 2 + i];
                    ps += v * s_av[0][col];
                    pd += v * s_av[1][col];
                }
            }
            ps += __shfl_xor_sync(0xFFFFFFFF, ps, 1);
            ps += __shfl_xor_sync(0xFFFFFFFF, ps, 2);
            pd += __shfl_xor_sync(0xFFFFFFFF, pd, 1);
            pd += __shfl_xor_sync(0xFFFFFFFF, pd, 2);
            if (kk == 0) {
                int lr = wm * 64 + mt * 16 + g + half * 8;
                atomicAdd(&s_pa[lr][0], ps);
                atomicAdd(&s_pa[lr][1], pd);
            }
        }
    }
    __syncthreads();
    if (tid < 128 && m0 + tid < M) {
        g_as[m0 + tid] = s_pa[tid][0];
        g_ad[m0 + tid] = s_pa[tid][1];
    }
}

__device__ __forceinline__ float lrelu(float x) {
    return x > 0.f ? x : NEG_SLOPE * x;
}

// ---------------- single-pass aggregation over bf16 h --------------------------
__global__ __launch_bounds__(256) void k_aggregate(const __nv_bfloat16* __restrict__ h,
                                                   const float* __restrict__ b,
                                                   float* __restrict__ out) {
    int v = (blockIdx.x * blockDim.x + threadIdx.x) >> 5;
    int lane = threadIdx.x & 31;
    if (v >= NN) return;
    int beg = g_rowptr[v];
    int end = g_rowptr[v + 1];
    float adv = g_ad[v];

    float4 acc = make_float4(0.f, 0.f, 0.f, 0.f);
    float den_p = 0.f;
    for (int c0 = beg; c0 < end; c0 += 32) {
        int n = min(32, end - c0);
        int s = 0;
        float w = 0.f;
        if (lane < n) {
            s = g_csr_src[c0 + lane];
            w = __expf(lrelu(__ldg(&g_as[s]) + adv));
        }
        den_p += w;
        for (int j = 0; j < n; j++) {
            float wb = __shfl_sync(0xFFFFFFFF, w, j);
            int sb = __shfl_sync(0xFFFFFFFF, s, j);
            uint2 u = *(const uint2*)&h[(size_t)sb * 128 + lane * 4];
            float2 f0 = __bfloat1622float2(*(__nv_bfloat162*)&u.x);
            float2 f1 = __bfloat1622float2(*(__nv_bfloat162*)&u.y);
            acc.x += wb * f0.x;
            acc.y += wb * f0.y;
            acc.z += wb * f1.x;
            acc.w += wb * f1.y;
        }
    }
#pragma unroll
    for (int off = 16; off > 0; off >>= 1)
        den_p += __shfl_xor_sync(0xFFFFFFFF, den_p, off);

    float inv = 1.f / den_p;
    float4 b4 = *(const float4*)&b[lane * 4];
    float4 o = make_float4(acc.x * inv + b4.x, acc.y * inv + b4.y,
                           acc.z * inv + b4.z, acc.w * inv + b4.w);
    *(float4*)&out[(size_t)v * 128 + lane * 4] = o;
}

// ---------------- pooling + fold (block 0) -------------------------------------
__device__ __forceinline__ int lower_bound_i(const int* a, int n, int key) {
    int lo = 0, hi = n;
    while (lo < hi) {
        int mid = (lo + hi) >> 1;
        if (a[mid] < key) lo = mid + 1;
        else hi = mid;
    }
    return lo;
}

__global__ __launch_bounds__(128) void k_pool(const float* __restrict__ x,
                                              const int* __restrict__ batch,
                                              const float* __restrict__ Wg,
                                              const float* __restrict__ bg,
                                              const float* __restrict__ Wo,
                                              const float* __restrict__ bo) {
    int g = blockIdx.x;
    int f = threadIdx.x;
    __shared__ int s_lo, s_hi;
    if (f == 0) s_lo = lower_bound_i(batch, NN, g);
    if (f == 1) s_hi = lower_bound_i(batch, NN, g + 1);
    __syncthreads();
    int lo = s_lo, hi = s_hi;
    float s = 0.f, mx = -1e30f;
    for (int i = lo; i < hi; i++) {
        float v = x[(size_t)i * 128 + f];
        s += v;
        mx = fmaxf(mx, v);
    }
    int cnt = hi - lo;
    g_mean[g * 128 + f] = s / (float)max(cnt, 1);
    g_max[g * 128 + f] = (cnt > 0) ? mx : 0.f;

    // fold g-feature path (block 0 only): wgo = Wg @ Wo[256:384], bgo = bg@.. + bo
    if (g == 0) {
        int t = f;
        if (t < GF * 2) {
            int k = t >> 1, c = t & 1;
            float acc = 0.f;
            for (int j = 0; j < EMB; j++)
                acc += Wg[k * EMB + j] * Wo[(256 + j) * 2 + c];
            g_wgo[t] = acc;
        } else if (t < GF * 2 + 2) {
            int c = t - GF * 2;
            float acc = bo[c];
            for (int j = 0; j < EMB; j++)
                acc += bg[j] * Wo[(256 + j) * 2 + c];
            g_bgo[c] = acc;
        }
    }
}

// ---------------- head ---------------------------------------------------------
__global__ __launch_bounds__(256) void k_head(const float* __restrict__ gfeat,
                                              const float* __restrict__ Wo,
                                              float* __restrict__ out) {
    int g = (blockIdx.x * blockDim.x + threadIdx.x) >> 5;
    int lane = threadIdx.x & 31;
    if (g >= GG) return;
    float s0 = 0.f, s1 = 0.f;
#pragma unroll
    for (int j = lane; j < 128; j += 32) {
        float mn = g_mean[g * 128 + j];
        float mx = g_max[g * 128 + j];
        s0 += mn * Wo[j * 2 + 0] + mx * Wo[(128 + j) * 2 + 0];
        s1 += mn * Wo[j * 2 + 1] + mx * Wo[(128 + j) * 2 + 1];
    }
    float gv = gfeat[g * GF + lane];
    s0 += gv * g_wgo[lane * 2 + 0];
    s1 += gv * g_wgo[lane * 2 + 1];
#pragma unroll
    for (int off = 16; off > 0; off >>= 1) {
        s0 += __shfl_xor_sync(0xFFFFFFFF, s0, off);
        s1 += __shfl_xor_sync(0xFFFFFFFF, s1, off);
    }
    if (lane == 0) {
        float l0 = s0 + g_bgo[0];
        float l1 = s1 + g_bgo[1];
        float m = fmaxf(l0, l1);
        float lse = m + logf(expf(l0 - m) + expf(l1 - m));
        out[g * 2 + 0] = l0 - lse;
        out[g * 2 + 1] = l1 - lse;
    }
}

// ---------------- launch --------------------------------------------------------
extern "C" void kernel_launch(void* const* d_in, const int* in_sizes, int n_in,
                              void* d_out, int out_size) {
    const float* x      = (const float*)d_in[0];
    const int*   edges  = (const int*)d_in[1];
    const int*   batch  = (const int*)d_in[2];
    const float* gfeat  = (const float*)d_in[3];
    const float* W1     = (const float*)d_in[4];
    const float* a1s    = (const float*)d_in[5];
    const float* a1d    = (const float*)d_in[6];
    const float* b1     = (const float*)d_in[7];
    const float* W2     = (const float*)d_in[8];
    const float* a2s    = (const float*)d_in[9];
    const float* a2d    = (const float*)d_in[10];
    const float* b2     = (const float*)d_in[11];
    const float* Wg     = (const float*)d_in[12];
    const float* bg     = (const float*)d_in[13];
    const float* Wo     = (const float*)d_in[14];
    const float* bo     = (const float*)d_in[15];
    float* out = (float*)d_out;

    const int* src = edges;
    const int* dst = edges + EE;

    __nv_bfloat16* d_hb; cudaGetSymbolAddress((void**)&d_hb, g_hb);
    float* d_x2; cudaGetSymbolAddress((void**)&d_x2, g_x2);

    // CSR build (stateless: explicit zero each call)
    k_zero<<<(NN + 255) / 256, 256>>>();
    k_hist<<<(EE + 255) / 256, 256>>>(dst);
    k_scan1<<<NBLK, SCAN_B>>>();
    k_scan3<<<(NN + 255) / 256, 256>>>();
    k_fill<<<(NN + EE + 255) / 256, 256>>>(src, dst);

    int gemm_blocks = (NN + BM - 1) / BM;
    int warp_blocks = (NN * 32 + 255) / 256;

    // layer 1 (GEMM computes h(bf16), as, ad)
    k_gemm_tc<<<gemm_blocks, 256>>>(x, W1, d_hb, a1s, a1d, NN, FIN);
    k_aggregate<<<warp_blocks, 256>>>(d_hb, b1, d_x2);

    // layer 2
    k_gemm_tc<<<gemm_blocks, 256>>>(d_x2, W2, d_hb, a2s, a2d, NN, EMB);
    k_aggregate<<<warp_blocks, 256>>>(d_hb, b2, d_x2);

    // pooling (+ fold) + head
    k_pool<<<GG, 128>>>(d_x2, batch, Wg, bg, Wo, bo);
    k_head<<<(GG * 32 + 255) / 256, 256>>>(gfeat, Wo, out);
}

// round 10
// speedup vs baseline: 1.8239x; 1.0625x over previous
#include <cuda_runtime.h>
#include <cuda_bf16.h>
#include <cstdint>

#define NN 50000
#define EE 800000
#define FIN 256
#define EMB 128
#define GF 32
#define GG 256
#define NEG_SLOPE 0.2f
#define ETOT (EE + NN)
#define SCAN_B 1024
#define NBLK ((NN + SCAN_B - 1) / SCAN_B)   // 49

// ---------------- scratch (device globals; no allocations allowed) -------------
__device__ __nv_bfloat16 g_hb[(size_t)NN * EMB];   // h in bf16 (gather payload)
__device__ float g_x2[(size_t)NN * EMB];           // layer output (fp32)
__device__ float g_as[NN];
__device__ float g_ad[NN];
__device__ int   g_counts[NN];
__device__ int   g_rowptr[NN + 1];
__device__ int   g_bsum[NBLK];
__device__ int   g_csr_src[ETOT];

// ---------------- CSR build ----------------------------------------------------
__global__ void k_zero() {
    int i = blockIdx.x * blockDim.x + threadIdx.x;
    int4* p = (int4*)g_counts;
    if (i < NN / 4) p[i] = make_int4(0, 0, 0, 0);
    // NN = 50000 = 4*12500, exact
}

__global__ void k_hist(const int* __restrict__ dst) {
    int e = blockIdx.x * blockDim.x + threadIdx.x;
    if (e < EE) atomicAdd(&g_counts[dst[e]], 1);
}

// local scan: each block scans 1024 (counts+1) values
__global__ __launch_bounds__(SCAN_B) void k_scan1() {
    __shared__ int warp_sums[32];
    int t = threadIdx.x;
    int lane = t & 31, w = t >> 5;
    int i = blockIdx.x * SCAN_B + t;
    int v = (i < NN) ? (g_counts[i] + 1) : 0;
    int x = v;
#pragma unroll
    for (int off = 1; off < 32; off <<= 1) {
        int y = __shfl_up_sync(0xFFFFFFFF, x, off);
        if (lane >= off) x += y;
    }
    if (lane == 31) warp_sums[w] = x;
    __syncthreads();
    if (w == 0) {
        int s = warp_sums[lane];
#pragma unroll
        for (int off = 1; off < 32; off <<= 1) {
            int y = __shfl_up_sync(0xFFFFFFFF, s, off);
            if (lane >= off) s += y;
        }
        warp_sums[lane] = s;
    }
    __syncthreads();
    if (i < NN) g_rowptr[i] = (w > 0 ? warp_sums[w - 1] : 0) + x - v;
    if (t == SCAN_B - 1) g_bsum[blockIdx.x] = warp_sums[31];
}

// fixup: every block redundantly scans the 49 block sums, then applies
__global__ __launch_bounds__(256) void k_scan3() {
    __shared__ int sh[NBLK];
    int t = threadIdx.x;
    if (t < NBLK) sh[t] = g_bsum[t];
    __syncthreads();
    if (t == 0) {
        int run = 0;
#pragma unroll
        for (int j = 0; j < NBLK; j++) {
            int tmp = sh[j];
            sh[j] = run;
            run += tmp;
        }
    }
    __syncthreads();
    int i = blockIdx.x * blockDim.x + t;
    if (i < NN) {
        int r = g_rowptr[i] + sh[i >> 10];
        g_rowptr[i] = r;
        g_counts[i] = r + 1;      // cursor past the self-loop slot
    }
    if (i == 0) g_rowptr[NN] = ETOT;
}

// self-loop fill + edge scatter (disjoint slots)
__global__ void k_fill(const int* __restrict__ src, const int* __restrict__ dst) {
    int t = blockIdx.x * blockDim.x + threadIdx.x;
    if (t < NN) {
        g_csr_src[g_rowptr[t]] = t;
    } else if (t < NN + EE) {
        int e = t - NN;
        int d = dst[e];
        int pos = atomicAdd(&g_counts[d], 1);
        g_csr_src[pos] = src[e];
    }
}

// ---------------- tf32 tensor-core GEMM + fused attention dots -----------------
__device__ __forceinline__ uint32_t f2tf32(float x) {
    uint32_t r;
    asm("cvt.rna.tf32.f32 %0, %1;" : "=r"(r) : "f"(x));
    return r;
}

__device__ __forceinline__ void mma_tf32(float* c, const uint32_t* a, const uint32_t* b) {
    asm volatile(
        "mma.sync.aligned.m16n8k8.row.col.f32.tf32.tf32.f32 "
        "{%0,%1,%2,%3}, {%4,%5,%6,%7}, {%8,%9}, {%0,%1,%2,%3};\n"
        : "+f"(c[0]), "+f"(c[1]), "+f"(c[2]), "+f"(c[3])
        : "r"(a[0]), "r"(a[1]), "r"(a[2]), "r"(a[3]), "r"(b[0]), "r"(b[1]));
}

#define BM 128
#define BKQ 16
#define AP 20
#define BP 132

__global__ __launch_bounds__(256) void k_gemm_tc(const float* __restrict__ A,
                                                 const float* __restrict__ B,
                                                 __nv_bfloat16* __restrict__ C,
                                                 const float* __restrict__ a_src,
                                                 const float* __restrict__ a_dst,
                                                 int M, int K) {
    __shared__ uint32_t As[2][BM][AP];
    __shared__ uint32_t Bs[2][BKQ][BP];
    __shared__ float s_av[2][128];
    __shared__ float s_pa[128][2];
    int tid = threadIdx.x;
    int lane = tid & 31, wid = tid >> 5;
    int wm = wid >> 2;
    int wn = wid & 3;
    int g = lane >> 2, kk = lane & 3;
    int m0 = blockIdx.x * BM;

    if (tid < 128) {
        s_av[0][tid] = a_src[tid];
        s_pa[tid][0] = 0.f;
        s_pa[tid][1] = 0.f;
    } else {
        s_av[1][tid - 128] = a_dst[tid - 128];
    }

    int arow = tid >> 2;
    int acol = (tid & 3) << 2;
    int brow = tid >> 5;
    int bcol = (tid & 31) << 2;

    float c[4][4][4];
#pragma unroll
    for (int mt = 0; mt < 4; mt++)
#pragma unroll
        for (int nt = 0; nt < 4; nt++)
#pragma unroll
            for (int i = 0; i < 4; i++) c[mt][nt][i] = 0.f;

    float4 ra[2], rb[2];
    const int nch = K / BKQ;

    {
        int r0 = m0 + arow, r1 = m0 + arow + 64;
        ra[0] = (r0 < M) ? *(const float4*)&A[(size_t)r0 * K + acol] : make_float4(0, 0, 0, 0);
        ra[1] = (r1 < M) ? *(const float4*)&A[(size_t)r1 * K + acol] : make_float4(0, 0, 0, 0);
        rb[0] = *(const float4*)&B[(size_t)brow * 128 + bcol];
        rb[1] = *(const float4*)&B[(size_t)(brow + 8) * 128 + bcol];
    }
    {
        uint32_t* pa0 = &As[0][arow][acol];
        pa0[0] = f2tf32(ra[0].x); pa0[1] = f2tf32(ra[0].y); pa0[2] = f2tf32(ra[0].z); pa0[3] = f2tf32(ra[0].w);
        uint32_t* pa1 = &As[0][arow + 64][acol];
        pa1[0] = f2tf32(ra[1].x); pa1[1] = f2tf32(ra[1].y); pa1[2] = f2tf32(ra[1].z); pa1[3] = f2tf32(ra[1].w);
        uint32_t* pb0 = &Bs[0][brow][bcol];
        pb0[0] = f2tf32(rb[0].x); pb0[1] = f2tf32(rb[0].y); pb0[2] = f2tf32(rb[0].z); pb0[3] = f2tf32(rb[0].w);
        uint32_t* pb1 = &Bs[0][brow + 8][bcol];
        pb1[0] = f2tf32(rb[1].x); pb1[1] = f2tf32(rb[1].y); pb1[2] = f2tf32(rb[1].z); pb1[3] = f2tf32(rb[1].w);
    }
    __syncthreads();

    for (int c0 = 0; c0 < nch; c0++) {
        int cur = c0 & 1;
        if (c0 + 1 < nch) {
            int k0 = (c0 + 1) * BKQ;
            int r0 = m0 + arow, r1 = m0 + arow + 64;
            ra[0] = (r0 < M) ? *(const float4*)&A[(size_t)r0 * K + k0 + acol] : make_float4(0, 0, 0, 0);
            ra[1] = (r1 < M) ? *(const float4*)&A[(size_t)r1 * K + k0 + acol] : make_float4(0, 0, 0, 0);
            rb[0] = *(const float4*)&B[(size_t)(k0 + brow) * 128 + bcol];
            rb[1] = *(const float4*)&B[(size_t)(k0 + brow + 8) * 128 + bcol];
        }
#pragma unroll
        for (int ks = 0; ks < 2; ks++) {
            int kb = ks * 8;
            uint32_t af[4][4], bf[4][2];
#pragma unroll
            for (int mt = 0; mt < 4; mt++) {
                int row = wm * 64 + mt * 16 + g;
                af[mt][0] = As[cur][row][kb + kk];
                af[mt][1] = As[cur][row + 8][kb + kk];
                af[mt][2] = As[cur][row][kb + kk + 4];
                af[mt][3] = As[cur][row + 8][kb + kk + 4];
            }
#pragma unroll
            for (int nt = 0; nt < 4; nt++) {
                int col = wn * 32 + nt * 8 + g;
                bf[nt][0] = Bs[cur][kb + kk][col];
                bf[nt][1] = Bs[cur][kb + kk + 4][col];
            }
#pragma unroll
            for (int mt = 0; mt < 4; mt++)
#pragma unroll
                for (int nt = 0; nt < 4; nt++)
                    mma_tf32(c[mt][nt], af[mt], bf[nt]);
        }
        if (c0 + 1 < nch) {
            int nb = (c0 + 1) & 1;
            uint32_t* pa0 = &As[nb][arow][acol];
            pa0[0] = f2tf32(ra[0].x); pa0[1] = f2tf32(ra[0].y); pa0[2] = f2tf32(ra[0].z); pa0[3] = f2tf32(ra[0].w);
            uint32_t* pa1 = &As[nb][arow + 64][acol];
            pa1[0] = f2tf32(ra[1].x); pa1[1] = f2tf32(ra[1].y); pa1[2] = f2tf32(ra[1].z); pa1[3] = f2tf32(ra[1].w);
            uint32_t* pb0 = &Bs[nb][brow][bcol];
            pb0[0] = f2tf32(rb[0].x); pb0[1] = f2tf32(rb[0].y); pb0[2] = f2tf32(rb[0].z); pb0[3] = f2tf32(rb[0].w);
            uint32_t* pb1 = &Bs[nb][brow + 8][bcol];
            pb1[0] = f2tf32(rb[1].x); pb1[1] = f2tf32(rb[1].y); pb1[2] = f2tf32(rb[1].z); pb1[3] = f2tf32(rb[1].w);
            __syncthreads();
        }
    }

    // epilogue: store C (bf16) + fused attention-dot partials (fp32)
#pragma unroll
    for (int mt = 0; mt < 4; mt++) {
        int row = m0 + wm * 64 + mt * 16 + g;
#pragma unroll
        for (int nt = 0; nt < 4; nt++) {
            int col = wn * 32 + nt * 8 + kk * 2;
            if (row < M)
                *(__nv_bfloat162*)&C[(size_t)row * 128 + col] =
                    __floats2bfloat162_rn(c[mt][nt][0], c[mt][nt][1]);
            if (row + 8 < M)
                *(__nv_bfloat162*)&C[(size_t)(row + 8) * 128 + col] =
                    __floats2bfloat162_rn(c[mt][nt][2], c[mt][nt][3]);
        }
#pragma unroll
        for (int half = 0; half < 2; half++) {
            float ps = 0.f, pd = 0.f;
#pragma unroll
            for (int nt = 0; nt < 4; nt++) {
#pragma unroll
                for (int i = 0; i < 2; i++) {
                    int col = wn * 32 + nt * 8 + kk * 2 + i;
                    float v = c[mt][nt][half * 2 + i];
                    ps += v * s_av[0][col];
                    pd += v * s_av[1][col];
                }
            }
            ps += __shfl_xor_sync(0xFFFFFFFF, ps, 1);
            ps += __shfl_xor_sync(0xFFFFFFFF, ps, 2);
            pd += __shfl_xor_sync(0xFFFFFFFF, pd, 1);
            pd += __shfl_xor_sync(0xFFFFFFFF, pd, 2);
            if (kk == 0) {
                int lr = wm * 64 + mt * 16 + g + half * 8;
                atomicAdd(&s_pa[lr][0], ps);
                atomicAdd(&s_pa[lr][1], pd);
            }
        }
    }
    __syncthreads();
    if (tid < 128 && m0 + tid < M) {
        g_as[m0 + tid] = s_pa[tid][0];
        g_ad[m0 + tid] = s_pa[tid][1];
    }
}

__device__ __forceinline__ float lrelu(float x) {
    return x > 0.f ? x : NEG_SLOPE * x;
}

// ---------------- single-pass aggregation, smem-staged weights -----------------
__global__ __launch_bounds__(256) void k_aggregate(const __nv_bfloat16* __restrict__ h,
                                                   const float* __restrict__ b,
                                                   float* __restrict__ out) {
    __shared__ int   sh_s[8][32];
    __shared__ float sh_w[8][32];
    int warp = threadIdx.x >> 5;
    int lane = threadIdx.x & 31;
    int v = (blockIdx.x * blockDim.x + threadIdx.x) >> 5;
    if (v >= NN) return;
    int beg = g_rowptr[v];
    int end = g_rowptr[v + 1];
    float adv = g_ad[v];

    float4 acc = make_float4(0.f, 0.f, 0.f, 0.f);
    float den_p = 0.f;
    for (int c0 = beg; c0 < end; c0 += 32) {
        int n = min(32, end - c0);
        int s = 0;
        float w = 0.f;
        if (lane < n) {
            s = g_csr_src[c0 + lane];
            w = __expf(lrelu(__ldg(&g_as[s]) + adv));
        }
        sh_s[warp][lane] = s;
        sh_w[warp][lane] = w;
        __syncwarp();
        den_p += w;
        // independent iterations: smem broadcast reads + parallel L2 gathers
#pragma unroll 4
        for (int j = 0; j < n; j++) {
            float wb = sh_w[warp][j];
            int sb = sh_s[warp][j];
            uint2 u = *(const uint2*)&h[(size_t)sb * 128 + lane * 4];
            float2 f0 = __bfloat1622float2(*(__nv_bfloat162*)&u.x);
            float2 f1 = __bfloat1622float2(*(__nv_bfloat162*)&u.y);
            acc.x += wb * f0.x;
            acc.y += wb * f0.y;
            acc.z += wb * f1.x;
            acc.w += wb * f1.y;
        }
        __syncwarp();
    }
#pragma unroll
    for (int off = 16; off > 0; off >>= 1)
        den_p += __shfl_xor_sync(0xFFFFFFFF, den_p, off);

    float inv = 1.f / den_p;
    float4 b4 = *(const float4*)&b[lane * 4];
    float4 o = make_float4(acc.x * inv + b4.x, acc.y * inv + b4.y,
                           acc.z * inv + b4.z, acc.w * inv + b4.w);
    *(float4*)&out[(size_t)v * 128 + lane * 4] = o;
}

// ---------------- fused pooling + g-feature + head (block per graph) -----------
__device__ __forceinline__ int lower_bound_i(const int* a, int n, int key) {
    int lo = 0, hi = n;
    while (lo < hi) {
        int mid = (lo + hi) >> 1;
        if (a[mid] < key) lo = mid + 1;
        else hi = mid;
    }
    return lo;
}

__global__ __launch_bounds__(128) void k_poolhead(const float* __restrict__ x,
                                                  const int* __restrict__ batch,
                                                  const float* __restrict__ gfeat,
                                                  const float* __restrict__ Wg,
                                                  const float* __restrict__ bg,
                                                  const float* __restrict__ Wo,
                                                  const float* __restrict__ bo,
                                                  float* __restrict__ out) {
    int g = blockIdx.x;
    int f = threadIdx.x;                 // 128 threads = one per feature
    __shared__ int s_lo, s_hi;
    __shared__ float sgf[GF];
    __shared__ float red[2][4];
    if (f == 0) s_lo = lower_bound_i(batch, NN, g);
    if (f == 1) s_hi = lower_bound_i(batch, NN, g + 1);
    if (f >= 64 && f < 64 + GF) sgf[f - 64] = gfeat[g * GF + (f - 64)];
    __syncthreads();
    int lo = s_lo, hi = s_hi;

    float s = 0.f, mx = -1e30f;
    for (int i = lo; i < hi; i++) {
        float v = x[(size_t)i * 128 + f];
        s += v;
        mx = fmaxf(mx, v);
    }
    int cnt = hi - lo;
    float mean = s / (float)max(cnt, 1);
    mx = (cnt > 0) ? mx : 0.f;

    // g_ft[f] = sum_k gfeat[g,k] * Wg[k,f] + bg[f]
    float gft = bg[f];
#pragma unroll
    for (int k = 0; k < GF; k++)
        gft += sgf[k] * Wg[k * EMB + f];

    // per-thread logit contributions
    float c0 = mean * Wo[f * 2 + 0] + mx * Wo[(128 + f) * 2 + 0] + gft * Wo[(256 + f) * 2 + 0];
    float c1 = mean * Wo[f * 2 + 1] + mx * Wo[(128 + f) * 2 + 1] + gft * Wo[(256 + f) * 2 + 1];
#pragma unroll
    for (int off = 16; off > 0; off >>= 1) {
        c0 += __shfl_xor_sync(0xFFFFFFFF, c0, off);
        c1 += __shfl_xor_sync(0xFFFFFFFF, c1, off);
    }
    int lane = f & 31, w = f >> 5;
    if (lane == 0) { red[0][w] = c0; red[1][w] = c1; }
    __syncthreads();
    if (f == 0) {
        float l0 = red[0][0] + red[0][1] + red[0][2] + red[0][3] + bo[0];
        float l1 = red[1][0] + red[1][1] + red[1][2] + red[1][3] + bo[1];
        float m = fmaxf(l0, l1);
        float lse = m + logf(expf(l0 - m) + expf(l1 - m));
        out[g * 2 + 0] = l0 - lse;
        out[g * 2 + 1] = l1 - lse;
    }
}

// ---------------- launch --------------------------------------------------------
extern "C" void kernel_launch(void* const* d_in, const int* in_sizes, int n_in,
                              void* d_out, int out_size) {
    const float* x      = (const float*)d_in[0];
    const int*   edges  = (const int*)d_in[1];
    const int*   batch  = (const int*)d_in[2];
    const float* gfeat  = (const float*)d_in[3];
    const float* W1     = (const float*)d_in[4];
    const float* a1s    = (const float*)d_in[5];
    const float* a1d    = (const float*)d_in[6];
    const float* b1     = (const float*)d_in[7];
    const float* W2     = (const float*)d_in[8];
    const float* a2s    = (const float*)d_in[9];
    const float* a2d    = (const float*)d_in[10];
    const float* b2     = (const float*)d_in[11];
    const float* Wg     = (const float*)d_in[12];
    const float* bg     = (const float*)d_in[13];
    const float* Wo     = (const float*)d_in[14];
    const float* bo     = (const float*)d_in[15];
    float* out = (float*)d_out;

    const int* src = edges;
    const int* dst = edges + EE;

    __nv_bfloat16* d_hb; cudaGetSymbolAddress((void**)&d_hb, g_hb);
    float* d_x2; cudaGetSymbolAddress((void**)&d_x2, g_x2);

    // CSR build (stateless, single stream)
    k_zero<<<(NN / 4 + 255) / 256, 256>>>();
    k_hist<<<(EE + 255) / 256, 256>>>(dst);
    k_scan1<<<NBLK, SCAN_B>>>();
    k_scan3<<<(NN + 255) / 256, 256>>>();
    k_fill<<<(NN + EE + 255) / 256, 256>>>(src, dst);

    int gemm_blocks = (NN + BM - 1) / BM;
    int warp_blocks = (NN * 32 + 255) / 256;

    // layer 1 (GEMM computes h(bf16), as, ad)
    k_gemm_tc<<<gemm_blocks, 256>>>(x, W1, d_hb, a1s, a1d, NN, FIN);
    k_aggregate<<<warp_blocks, 256>>>(d_hb, b1, d_x2);

    // layer 2
    k_gemm_tc<<<gemm_blocks, 256>>>(d_x2, W2, d_hb, a2s, a2d, NN, EMB);
    k_aggregate<<<warp_blocks, 256>>>(d_hb, b2, d_x2);

    // fused pooling + g-feature + head
    k_poolhead<<<GG, 128>>>(d_x2, batch, gfeat, Wg, bg, Wo, bo, out);
}

// round 11
// speedup vs baseline: 1.9042x; 1.0440x over previous
#include <cuda_runtime.h>
#include <cuda_bf16.h>
#include <cstdint>

#define NN 50000
#define EE 800000
#define FIN 256
#define EMB 128
#define GF 32
#define GG 256
#define NEG_SLOPE 0.2f
#define ETOT (EE + NN)
#define SCAN_B 1024
#define NBLK ((NN + SCAN_B - 1) / SCAN_B)   // 49
#define BM 128
#define BKQ 16
#define AP 20
#define BP 132
#define GEMM_BLOCKS ((NN + BM - 1) / BM)            // 391
#define FILL_BLOCKS ((NN + EE + 255) / 256)         // 3321

// ---------------- scratch (device globals; no allocations allowed) -------------
__device__ __nv_bfloat16 g_hb[(size_t)NN * EMB];   // h in bf16 (gather payload)
__device__ float g_x2[(size_t)NN * EMB];           // layer output (fp32)
__device__ float g_as[NN];
__device__ float g_ad[NN];
__device__ int   g_counts[NN];
__device__ int   g_rowptr[NN + 1];
__device__ int   g_bsum[NBLK];
__device__ int   g_pos[EE];                        // per-edge slot within its dst row
__device__ int   g_csr_src[ETOT];

// ---------------- CSR build ----------------------------------------------------
__global__ void k_zero() {
    int i = blockIdx.x * blockDim.x + threadIdx.x;
    int4* p = (int4*)g_counts;
    if (i < NN / 4) p[i] = make_int4(0, 0, 0, 0);   // NN = 4*12500, exact
}

// histogram + record each edge's slot within its destination row
__global__ void k_hist(const int* __restrict__ dst) {
    int e = blockIdx.x * blockDim.x + threadIdx.x;
    if (e < EE) {
        int d = dst[e];
        g_pos[e] = atomicAdd(&g_counts[d], 1);
    }
}

// local scan: each block scans 1024 (counts+1) values
__global__ __launch_bounds__(SCAN_B) void k_scan1() {
    __shared__ int warp_sums[32];
    int t = threadIdx.x;
    int lane = t & 31, w = t >> 5;
    int i = blockIdx.x * SCAN_B + t;
    int v = (i < NN) ? (g_counts[i] + 1) : 0;
    int x = v;
#pragma unroll
    for (int off = 1; off < 32; off <<= 1) {
        int y = __shfl_up_sync(0xFFFFFFFF, x, off);
        if (lane >= off) x += y;
    }
    if (lane == 31) warp_sums[w] = x;
    __syncthreads();
    if (w == 0) {
        int s = warp_sums[lane];
#pragma unroll
        for (int off = 1; off < 32; off <<= 1) {
            int y = __shfl_up_sync(0xFFFFFFFF, s, off);
            if (lane >= off) s += y;
        }
        warp_sums[lane] = s;
    }
    __syncthreads();
    if (i < NN) g_rowptr[i] = (w > 0 ? warp_sums[w - 1] : 0) + x - v;
    if (t == SCAN_B - 1) g_bsum[blockIdx.x] = warp_sums[31];
}

// fixup: every block redundantly scans the 49 block sums, then applies
__global__ __launch_bounds__(256) void k_scan3() {
    __shared__ int sh[NBLK];
    int t = threadIdx.x;
    if (t < NBLK) sh[t] = g_bsum[t];
    __syncthreads();
    if (t == 0) {
        int run = 0;
#pragma unroll
        for (int j = 0; j < NBLK; j++) {
            int tmp = sh[j];
            sh[j] = run;
            run += tmp;
        }
    }
    __syncthreads();
    int i = blockIdx.x * blockDim.x + t;
    if (i < NN) g_rowptr[i] = g_rowptr[i] + sh[i >> 10];
    if (i == 0) g_rowptr[NN] = ETOT;
}

// ---------------- tf32 tensor-core GEMM body (device inline) -------------------
__device__ __forceinline__ uint32_t f2tf32(float x) {
    uint32_t r;
    asm("cvt.rna.tf32.f32 %0, %1;" : "=r"(r) : "f"(x));
    return r;
}

__device__ __forceinline__ void mma_tf32(float* c, const uint32_t* a, const uint32_t* b) {
    asm volatile(
        "mma.sync.aligned.m16n8k8.row.col.f32.tf32.tf32.f32 "
        "{%0,%1,%2,%3}, {%4,%5,%6,%7}, {%8,%9}, {%0,%1,%2,%3};\n"
        : "+f"(c[0]), "+f"(c[1]), "+f"(c[2]), "+f"(c[3])
        : "r"(a[0]), "r"(a[1]), "r"(a[2]), "r"(a[3]), "r"(b[0]), "r"(b[1]));
}

__device__ __forceinline__ void gemm_body(int m0,
                                          const float* __restrict__ A,
                                          const float* __restrict__ B,
                                          __nv_bfloat16* __restrict__ C,
                                          const float* __restrict__ a_src,
                                          const float* __restrict__ a_dst,
                                          int M, int K) {
    __shared__ uint32_t As[2][BM][AP];
    __shared__ uint32_t Bs[2][BKQ][BP];
    __shared__ float s_av[2][128];
    __shared__ float s_pa[128][2];
    int tid = threadIdx.x;
    int lane = tid & 31, wid = tid >> 5;
    int wm = wid >> 2;
    int wn = wid & 3;
    int g = lane >> 2, kk = lane & 3;

    if (tid < 128) {
        s_av[0][tid] = a_src[tid];
        s_pa[tid][0] = 0.f;
        s_pa[tid][1] = 0.f;
    } else {
        s_av[1][tid - 128] = a_dst[tid - 128];
    }

    int arow = tid >> 2;
    int acol = (tid & 3) << 2;
    int brow = tid >> 5;
    int bcol = (tid & 31) << 2;

    float c[4][4][4];
#pragma unroll
    for (int mt = 0; mt < 4; mt++)
#pragma unroll
        for (int nt = 0; nt < 4; nt++)
#pragma unroll
            for (int i = 0; i < 4; i++) c[mt][nt][i] = 0.f;

    float4 ra[2], rb[2];
    const int nch = K / BKQ;

    {
        int r0 = m0 + arow, r1 = m0 + arow + 64;
        ra[0] = (r0 < M) ? *(const float4*)&A[(size_t)r0 * K + acol] : make_float4(0, 0, 0, 0);
        ra[1] = (r1 < M) ? *(const float4*)&A[(size_t)r1 * K + acol] : make_float4(0, 0, 0, 0);
        rb[0] = *(const float4*)&B[(size_t)brow * 128 + bcol];
        rb[1] = *(const float4*)&B[(size_t)(brow + 8) * 128 + bcol];
    }
    {
        uint32_t* pa0 = &As[0][arow][acol];
        pa0[0] = f2tf32(ra[0].x); pa0[1] = f2tf32(ra[0].y); pa0[2] = f2tf32(ra[0].z); pa0[3] = f2tf32(ra[0].w);
        uint32_t* pa1 = &As[0][arow + 64][acol];
        pa1[0] = f2tf32(ra[1].x); pa1[1] = f2tf32(ra[1].y); pa1[2] = f2tf32(ra[1].z); pa1[3] = f2tf32(ra[1].w);
        uint32_t* pb0 = &Bs[0][brow][bcol];
        pb0[0] = f2tf32(rb[0].x); pb0[1] = f2tf32(rb[0].y); pb0[2] = f2tf32(rb[0].z); pb0[3] = f2tf32(rb[0].w);
        uint32_t* pb1 = &Bs[0][brow + 8][bcol];
        pb1[0] = f2tf32(rb[1].x); pb1[1] = f2tf32(rb[1].y); pb1[2] = f2tf32(rb[1].z); pb1[3] = f2tf32(rb[1].w);
    }
    __syncthreads();

    for (int c0 = 0; c0 < nch; c0++) {
        int cur = c0 & 1;
        if (c0 + 1 < nch) {
            int k0 = (c0 + 1) * BKQ;
            int r0 = m0 + arow, r1 = m0 + arow + 64;
            ra[0] = (r0 < M) ? *(const float4*)&A[(size_t)r0 * K + k0 + acol] : make_float4(0, 0, 0, 0);
            ra[1] = (r1 < M) ? *(const float4*)&A[(size_t)r1 * K + k0 + acol] : make_float4(0, 0, 0, 0);
            rb[0] = *(const float4*)&B[(size_t)(k0 + brow) * 128 + bcol];
            rb[1] = *(const float4*)&B[(size_t)(k0 + brow + 8) * 128 + bcol];
        }
#pragma unroll
        for (int ks = 0; ks < 2; ks++) {
            int kb = ks * 8;
            uint32_t af[4][4], bf[4][2];
#pragma unroll
            for (int mt = 0; mt < 4; mt++) {
                int row = wm * 64 + mt * 16 + g;
                af[mt][0] = As[cur][row][kb + kk];
                af[mt][1] = As[cur][row + 8][kb + kk];
                af[mt][2] = As[cur][row][kb + kk + 4];
                af[mt][3] = As[cur][row + 8][kb + kk + 4];
            }
#pragma unroll
            for (int nt = 0; nt < 4; nt++) {
                int col = wn * 32 + nt * 8 + g;
                bf[nt][0] = Bs[cur][kb + kk][col];
                bf[nt][1] = Bs[cur][kb + kk + 4][col];
            }
#pragma unroll
            for (int mt = 0; mt < 4; mt++)
#pragma unroll
                for (int nt = 0; nt < 4; nt++)
                    mma_tf32(c[mt][nt], af[mt], bf[nt]);
        }
        if (c0 + 1 < nch) {
            int nb = (c0 + 1) & 1;
            uint32_t* pa0 = &As[nb][arow][acol];
            pa0[0] = f2tf32(ra[0].x); pa0[1] = f2tf32(ra[0].y); pa0[2] = f2tf32(ra[0].z); pa0[3] = f2tf32(ra[0].w);
            uint32_t* pa1 = &As[nb][arow + 64][acol];
            pa1[0] = f2tf32(ra[1].x); pa1[1] = f2tf32(ra[1].y); pa1[2] = f2tf32(ra[1].z); pa1[3] = f2tf32(ra[1].w);
            uint32_t* pb0 = &Bs[nb][brow][bcol];
            pb0[0] = f2tf32(rb[0].x); pb0[1] = f2tf32(rb[0].y); pb0[2] = f2tf32(rb[0].z); pb0[3] = f2tf32(rb[0].w);
            uint32_t* pb1 = &Bs[nb][brow + 8][bcol];
            pb1[0] = f2tf32(rb[1].x); pb1[1] = f2tf32(rb[1].y); pb1[2] = f2tf32(rb[1].z); pb1[3] = f2tf32(rb[1].w);
            __syncthreads();
        }
    }

    // epilogue: store C (bf16) + fused attention-dot partials (fp32)
#pragma unroll
    for (int mt = 0; mt < 4; mt++) {
        int row = m0 + wm * 64 + mt * 16 + g;
#pragma unroll
        for (int nt = 0; nt < 4; nt++) {
            int col = wn * 32 + nt * 8 + kk * 2;
            if (row < M)
                *(__nv_bfloat162*)&C[(size_t)row * 128 + col] =
                    __floats2bfloat162_rn(c[mt][nt][0], c[mt][nt][1]);
            if (row + 8 < M)
                *(__nv_bfloat162*)&C[(size_t)(row + 8) * 128 + col] =
                    __floats2bfloat162_rn(c[mt][nt][2], c[mt][nt][3]);
        }
#pragma unroll
        for (int half = 0; half < 2; half++) {
            float ps = 0.f, pd = 0.f;
#pragma unroll
            for (int nt = 0; nt < 4; nt++) {
#pragma unroll
                for (int i = 0; i < 2; i++) {
                    int col = wn * 32 + nt * 8 + kk * 2 + i;
                    float v = c[mt][nt][half * 2 + i];
                    ps += v * s_av[0][col];
                    pd += v * s_av[1][col];
                }
            }
            ps += __shfl_xor_sync(0xFFFFFFFF, ps, 1);
            ps += __shfl_xor_sync(0xFFFFFFFF, ps, 2);
            pd += __shfl_xor_sync(0xFFFFFFFF, pd, 1);
            pd += __shfl_xor_sync(0xFFFFFFFF, pd, 2);
            if (kk == 0) {
                int lr = wm * 64 + mt * 16 + g + half * 8;
                atomicAdd(&s_pa[lr][0], ps);
                atomicAdd(&s_pa[lr][1], pd);
            }
        }
    }
    __syncthreads();
    if (tid < 128 && m0 + tid < M) {
        g_as[m0 + tid] = s_pa[tid][0];
        g_ad[m0 + tid] = s_pa[tid][1];
    }
}

// plain GEMM kernel (layer 2)
__global__ __launch_bounds__(256) void k_gemm_tc(const float* __restrict__ A,
                                                 const float* __restrict__ B,
                                                 __nv_bfloat16* __restrict__ C,
                                                 const float* __restrict__ a_src,
                                                 const float* __restrict__ a_dst,
                                                 int M, int K) {
    gemm_body(blockIdx.x * BM, A, B, C, a_src, a_dst, M, K);
}

// fused GEMM1 + CSR fill (block-partitioned; fill has no atomics thanks to g_pos)
__global__ __launch_bounds__(256) void k_gemm_fill(const float* __restrict__ A,
                                                   const float* __restrict__ B,
                                                   __nv_bfloat16* __restrict__ C,
                                                   const float* __restrict__ a_src,
                                                   const float* __restrict__ a_dst,
                                                   int M, int K,
                                                   const int* __restrict__ src,
                                                   const int* __restrict__ dst) {
    if (blockIdx.x < GEMM_BLOCKS) {
        gemm_body(blockIdx.x * BM, A, B, C, a_src, a_dst, M, K);
    } else {
        int t = (blockIdx.x - GEMM_BLOCKS) * blockDim.x + threadIdx.x;
        if (t < NN) {
            g_csr_src[g_rowptr[t]] = t;                       // self loop first
        } else if (t < NN + EE) {
            int e = t - NN;
            int d = dst[e];
            g_csr_src[g_rowptr[d] + 1 + g_pos[e]] = src[e];   // pure store
        }
    }
}

__device__ __forceinline__ float lrelu(float x) {
    return x > 0.f ? x : NEG_SLOPE * x;
}

// ---------------- single-pass aggregation, smem-staged weights -----------------
__global__ __launch_bounds__(256) void k_aggregate(const __nv_bfloat16* __restrict__ h,
                                                   const float* __restrict__ b,
                                                   float* __restrict__ out) {
    __shared__ int   sh_s[8][32];
    __shared__ float sh_w[8][32];
    int warp = threadIdx.x >> 5;
    int lane = threadIdx.x & 31;
    int v = (blockIdx.x * blockDim.x + threadIdx.x) >> 5;
    if (v >= NN) return;
    int beg = g_rowptr[v];
    int end = g_rowptr[v + 1];
    float adv = g_ad[v];

    float4 acc = make_float4(0.f, 0.f, 0.f, 0.f);
    float den_p = 0.f;
    for (int c0 = beg; c0 < end; c0 += 32) {
        int n = min(32, end - c0);
        int s = 0;
        float w = 0.f;
        if (lane < n) {
            s = g_csr_src[c0 + lane];
            w = __expf(lrelu(__ldg(&g_as[s]) + adv));
        }
        sh_s[warp][lane] = s;
        sh_w[warp][lane] = w;
        __syncwarp();
        den_p += w;
#pragma unroll 4
        for (int j = 0; j < n; j++) {
            float wb = sh_w[warp][j];
            int sb = sh_s[warp][j];
            uint2 u = *(const uint2*)&h[(size_t)sb * 128 + lane * 4];
            float2 f0 = __bfloat1622float2(*(__nv_bfloat162*)&u.x);
            float2 f1 = __bfloat1622float2(*(__nv_bfloat162*)&u.y);
            acc.x += wb * f0.x;
            acc.y += wb * f0.y;
            acc.z += wb * f1.x;
            acc.w += wb * f1.y;
        }
        __syncwarp();
    }
#pragma unroll
    for (int off = 16; off > 0; off >>= 1)
        den_p += __shfl_xor_sync(0xFFFFFFFF, den_p, off);

    float inv = 1.f / den_p;
    float4 b4 = *(const float4*)&b[lane * 4];
    float4 o = make_float4(acc.x * inv + b4.x, acc.y * inv + b4.y,
                           acc.z * inv + b4.z, acc.w * inv + b4.w);
    *(float4*)&out[(size_t)v * 128 + lane * 4] = o;
}

// ---------------- fused pooling + g-feature + head (block per graph) -----------
__device__ __forceinline__ int lower_bound_i(const int* a, int n, int key) {
    int lo = 0, hi = n;
    while (lo < hi) {
        int mid = (lo + hi) >> 1;
        if (a[mid] < key) lo = mid + 1;
        else hi = mid;
    }
    return lo;
}

__global__ __launch_bounds__(128) void k_poolhead(const float* __restrict__ x,
                                                  const int* __restrict__ batch,
                                                  const float* __restrict__ gfeat,
                                                  const float* __restrict__ Wg,
                                                  const float* __restrict__ bg,
                                                  const float* __restrict__ Wo,
                                                  const float* __restrict__ bo,
                                                  float* __restrict__ out) {
    int g = blockIdx.x;
    int f = threadIdx.x;
    __shared__ int s_lo, s_hi;
    __shared__ float sgf[GF];
    __shared__ float red[2][4];
    if (f == 0) s_lo = lower_bound_i(batch, NN, g);
    if (f == 1) s_hi = lower_bound_i(batch, NN, g + 1);
    if (f >= 64 && f < 64 + GF) sgf[f - 64] = gfeat[g * GF + (f - 64)];
    __syncthreads();
    int lo = s_lo, hi = s_hi;

    float s = 0.f, mx = -1e30f;
    for (int i = lo; i < hi; i++) {
        float v = x[(size_t)i * 128 + f];
        s += v;
        mx = fmaxf(mx, v);
    }
    int cnt = hi - lo;
    float mean = s / (float)max(cnt, 1);
    mx = (cnt > 0) ? mx : 0.f;

    float gft = bg[f];
#pragma unroll
    for (int k = 0; k < GF; k++)
        gft += sgf[k] * Wg[k * EMB + f];

    float c0 = mean * Wo[f * 2 + 0] + mx * Wo[(128 + f) * 2 + 0] + gft * Wo[(256 + f) * 2 + 0];
    float c1 = mean * Wo[f * 2 + 1] + mx * Wo[(128 + f) * 2 + 1] + gft * Wo[(256 + f) * 2 + 1];
#pragma unroll
    for (int off = 16; off > 0; off >>= 1) {
        c0 += __shfl_xor_sync(0xFFFFFFFF, c0, off);
        c1 += __shfl_xor_sync(0xFFFFFFFF, c1, off);
    }
    int lane = f & 31, w = f >> 5;
    if (lane == 0) { red[0][w] = c0; red[1][w] = c1; }
    __syncthreads();
    if (f == 0) {
        float l0 = red[0][0] + red[0][1] + red[0][2] + red[0][3] + bo[0];
        float l1 = red[1][0] + red[1][1] + red[1][2] + red[1][3] + bo[1];
        float m = fmaxf(l0, l1);
        float lse = m + logf(expf(l0 - m) + expf(l1 - m));
        out[g * 2 + 0] = l0 - lse;
        out[g * 2 + 1] = l1 - lse;
    }
}

// ---------------- launch --------------------------------------------------------
extern "C" void kernel_launch(void* const* d_in, const int* in_sizes, int n_in,
                              void* d_out, int out_size) {
    const float* x      = (const float*)d_in[0];
    const int*   edges  = (const int*)d_in[1];
    const int*   batch  = (const int*)d_in[2];
    const float* gfeat  = (const float*)d_in[3];
    const float* W1     = (const float*)d_in[4];
    const float* a1s    = (const float*)d_in[5];
    const float* a1d    = (const float*)d_in[6];
    const float* b1     = (const float*)d_in[7];
    const float* W2     = (const float*)d_in[8];
    const float* a2s    = (const float*)d_in[9];
    const float* a2d    = (const float*)d_in[10];
    const float* b2     = (const float*)d_in[11];
    const float* Wg     = (const float*)d_in[12];
    const float* bg     = (const float*)d_in[13];
    const float* Wo     = (const float*)d_in[14];
    const float* bo     = (const float*)d_in[15];
    float* out = (float*)d_out;

    const int* src = edges;
    const int* dst = edges + EE;

    __nv_bfloat16* d_hb; cudaGetSymbolAddress((void**)&d_hb, g_hb);
    float* d_x2; cudaGetSymbolAddress((void**)&d_x2, g_x2);

    // CSR prefix (zero -> hist(+pos) -> scan1 -> scan3)
    k_zero<<<(NN / 4 + 255) / 256, 256>>>();
    k_hist<<<(EE + 255) / 256, 256>>>(dst);
    k_scan1<<<NBLK, SCAN_B>>>();
    k_scan3<<<(NN + 255) / 256, 256>>>();

    int warp_blocks = (NN * 32 + 255) / 256;

    // fused: GEMM1 (h, as, ad) + CSR fill (atomic-free, hidden under GEMM)
    k_gemm_fill<<<GEMM_BLOCKS + FILL_BLOCKS, 256>>>(x, W1, d_hb, a1s, a1d, NN, FIN, src, dst);
    k_aggregate<<<warp_blocks, 256>>>(d_hb, b1, d_x2);

    // layer 2
    k_gemm_tc<<<GEMM_BLOCKS, 256>>>(d_x2, W2, d_hb, a2s, a2d, NN, EMB);
    k_aggregate<<<warp_blocks, 256>>>(d_hb, b2, d_x2);

    // fused pooling + g-feature + head
    k_poolhead<<<GG, 128>>>(d_x2, batch, gfeat, Wg, bg, Wo, bo, out);
}

// round 13
// speedup vs baseline: 2.1096x; 1.1079x over previous
#include <cuda_runtime.h>
#include <cuda_bf16.h>
#include <cstdint>

#define NN 50000
#define EE 800000
#define FIN 256
#define EMB 128
#define GF 32
#define GG 256
#define NEG_SLOPE 0.2f
#define ETOT (EE + NN)
#define SCAN_B 1024
#define NBLK ((NN + SCAN_B - 1) / SCAN_B)   // 49
#define BM 128
#define BKE 32                               // k-elements per chunk (bf16)
#define AP 20                                // A smem stride in uint32 (16 pairs + pad)
#define BP 132                               // B smem stride in uint32
#define GEMM_BLOCKS ((NN + BM - 1) / BM)     // 391
#define FILL_BLOCKS ((NN + EE + 255) / 256)  // 3321

// ---------------- scratch (device globals; no allocations allowed) -------------
__device__ __nv_bfloat16 g_hb[(size_t)NN * EMB];   // h in bf16 (gather payload)
__device__ float g_x2[(size_t)NN * EMB];           // layer output (fp32)
__device__ float g_as[NN];
__device__ float g_ad[NN];
__device__ int   g_counts[NN];
__device__ int   g_rowptr[NN + 1];
__device__ int   g_bsum[NBLK];
__device__ int   g_pos[EE];                        // per-edge slot within its dst row
__device__ int   g_csr_src[ETOT];

// ---------------- CSR build ----------------------------------------------------
__global__ void k_zero() {
    int i = blockIdx.x * blockDim.x + threadIdx.x;
    int4* p = (int4*)g_counts;
    if (i < NN / 4) p[i] = make_int4(0, 0, 0, 0);   // NN = 4*12500, exact
}

// histogram + record each edge's slot within its destination row
__global__ void k_hist(const int* __restrict__ dst) {
    int e = blockIdx.x * blockDim.x + threadIdx.x;
    if (e < EE) {
        int d = dst[e];
        g_pos[e] = atomicAdd(&g_counts[d], 1);
    }
}

// local scan: each block scans 1024 (counts+1) values
__global__ __launch_bounds__(SCAN_B) void k_scan1() {
    __shared__ int warp_sums[32];
    int t = threadIdx.x;
    int lane = t & 31, w = t >> 5;
    int i = blockIdx.x * SCAN_B + t;
    int v = (i < NN) ? (g_counts[i] + 1) : 0;
    int x = v;
#pragma unroll
    for (int off = 1; off < 32; off <<= 1) {
        int y = __shfl_up_sync(0xFFFFFFFF, x, off);
        if (lane >= off) x += y;
    }
    if (lane == 31) warp_sums[w] = x;
    __syncthreads();
    if (w == 0) {
        int s = warp_sums[lane];
#pragma unroll
        for (int off = 1; off < 32; off <<= 1) {
            int y = __shfl_up_sync(0xFFFFFFFF, s, off);
            if (lane >= off) s += y;
        }
        warp_sums[lane] = s;
    }
    __syncthreads();
    if (i < NN) g_rowptr[i] = (w > 0 ? warp_sums[w - 1] : 0) + x - v;
    if (t == SCAN_B - 1) g_bsum[blockIdx.x] = warp_sums[31];
}

// fixup: every block redundantly scans the 49 block sums, then applies
__global__ __launch_bounds__(256) void k_scan3() {
    __shared__ int sh[NBLK];
    int t = threadIdx.x;
    if (t < NBLK) sh[t] = g_bsum[t];
    __syncthreads();
    if (t == 0) {
        int run = 0;
#pragma unroll
        for (int j = 0; j < NBLK; j++) {
            int tmp = sh[j];
            sh[j] = run;
            run += tmp;
        }
    }
    __syncthreads();
    int i = blockIdx.x * blockDim.x + t;
    if (i < NN) g_rowptr[i] = g_rowptr[i] + sh[i >> 10];
    if (i == 0) g_rowptr[NN] = ETOT;
}

// ---------------- bf16 tensor-core GEMM body (device inline) -------------------
__device__ __forceinline__ uint32_t pack_bf16(float lo, float hi) {
    __nv_bfloat162 t = __floats2bfloat162_rn(lo, hi);
    return *(uint32_t*)&t;
}

__device__ __forceinline__ void mma_bf16(float* c, const uint32_t* a, const uint32_t* b) {
    asm volatile(
        "mma.sync.aligned.m16n8k16.row.col.f32.bf16.bf16.f32 "
        "{%0,%1,%2,%3}, {%4,%5,%6,%7}, {%8,%9}, {%0,%1,%2,%3};\n"
        : "+f"(c[0]), "+f"(c[1]), "+f"(c[2]), "+f"(c[3])
        : "r"(a[0]), "r"(a[1]), "r"(a[2]), "r"(a[3]), "r"(b[0]), "r"(b[1]));
}

__device__ __forceinline__ void gemm_body(int m0,
                                          const float* __restrict__ A,
                                          const float* __restrict__ B,
                                          __nv_bfloat16* __restrict__ C,
                                          const float* __restrict__ a_src,
                                          const float* __restrict__ a_dst,
                                          int M, int K) {
    // smem holds bf16x2 pairs packed in uint32; pair index = k/2
    __shared__ uint32_t As[2][BM][AP];        // 16 pairs (32 k) per row + pad
    __shared__ uint32_t Bs[2][BKE / 2][BP];   // 16 pair-rows x 128 cols
    __shared__ float s_av[2][128];
    __shared__ float s_pa[128][2];
    int tid = threadIdx.x;
    int lane = tid & 31, wid = tid >> 5;
    int wm = wid >> 2;
    int wn = wid & 3;
    int g = lane >> 2, kk = lane & 3;

    if (tid < 128) {
        s_av[0][tid] = a_src[tid];
        s_pa[tid][0] = 0.f;
        s_pa[tid][1] = 0.f;
    } else {
        s_av[1][tid - 128] = a_dst[tid - 128];
    }

    // loader mapping
    int arow = tid >> 2;              // 0..63 (and +64)
    int apc = (tid & 3) << 2;         // pair-col base: 0,4,8,12
    int ak = apc << 1;                // k-element offset: 0,8,16,24
    int bk2 = tid >> 5;               // 0..7 (and +8) pair-row
    int bcol = (tid & 31) << 2;       // 0..124

    float c[4][4][4];
#pragma unroll
    for (int mt = 0; mt < 4; mt++)
#pragma unroll
        for (int nt = 0; nt < 4; nt++)
#pragma unroll
            for (int i = 0; i < 4; i++) c[mt][nt][i] = 0.f;

    float4 ra[2][2], rb[2][2];
    const int nch = K / BKE;

    // prologue: fetch chunk 0
#pragma unroll
    for (int r = 0; r < 2; r++) {
        int row = m0 + arow + r * 64;
        if (row < M) {
            ra[r][0] = *(const float4*)&A[(size_t)row * K + ak];
            ra[r][1] = *(const float4*)&A[(size_t)row * K + ak + 4];
        } else {
            ra[r][0] = make_float4(0, 0, 0, 0);
            ra[r][1] = make_float4(0, 0, 0, 0);
        }
    }
#pragma unroll
    for (int s = 0; s < 2; s++) {
        int krow = (bk2 + s * 8) * 2;
        rb[s][0] = *(const float4*)&B[(size_t)krow * 128 + bcol];
        rb[s][1] = *(const float4*)&B[(size_t)(krow + 1) * 128 + bcol];
    }
    {
#pragma unroll
        for (int r = 0; r < 2; r++) {
            uint32_t* pa = &As[0][arow + r * 64][apc];
            pa[0] = pack_bf16(ra[r][0].x, ra[r][0].y);
            pa[1] = pack_bf16(ra[r][0].z, ra[r][0].w);
            pa[2] = pack_bf16(ra[r][1].x, ra[r][1].y);
            pa[3] = pack_bf16(ra[r][1].z, ra[r][1].w);
        }
#pragma unroll
        for (int s = 0; s < 2; s++) {
            uint32_t* pb = &Bs[0][bk2 + s * 8][bcol];
            pb[0] = pack_bf16(rb[s][0].x, rb[s][1].x);
            pb[1] = pack_bf16(rb[s][0].y, rb[s][1].y);
            pb[2] = pack_bf16(rb[s][0].z, rb[s][1].z);
            pb[3] = pack_bf16(rb[s][0].w, rb[s][1].w);
        }
    }
    __syncthreads();

    for (int c0 = 0; c0 < nch; c0++) {
        int cur = c0 & 1;
        if (c0 + 1 < nch) {
            int k0 = (c0 + 1) * BKE;
#pragma unroll
            for (int r = 0; r < 2; r++) {
                int row = m0 + arow + r * 64;
                if (row < M) {
                    ra[r][0] = *(const float4*)&A[(size_t)row * K + k0 + ak];
                    ra[r][1] = *(const float4*)&A[(size_t)row * K + k0 + ak + 4];
                } else {
                    ra[r][0] = make_float4(0, 0, 0, 0);
                    ra[r][1] = make_float4(0, 0, 0, 0);
                }
            }
#pragma unroll
            for (int s = 0; s < 2; s++) {
                int krow = k0 + (bk2 + s * 8) * 2;
                rb[s][0] = *(const float4*)&B[(size_t)krow * 128 + bcol];
                rb[s][1] = *(const float4*)&B[(size_t)(krow + 1) * 128 + bcol];
            }
        }
        // 2 k16 MMA steps per 32-element chunk
#pragma unroll
        for (int ks = 0; ks < 2; ks++) {
            int kb = ks * 8;                      // pair-index base
            uint32_t af[4][4], bf[4][2];
#pragma unroll
            for (int mt = 0; mt < 4; mt++) {
                int row = wm * 64 + mt * 16 + g;
                af[mt][0] = As[cur][row][kb + kk];
                af[mt][1] = As[cur][row + 8][kb + kk];
                af[mt][2] = As[cur][row][kb + kk + 4];
                af[mt][3] = As[cur][row + 8][kb + kk + 4];
            }
#pragma unroll
            for (int nt = 0; nt < 4; nt++) {
                int col = wn * 32 + nt * 8 + g;
                bf[nt][0] = Bs[cur][kb + kk][col];
                bf[nt][1] = Bs[cur][kb + kk + 4][col];
            }
#pragma unroll
            for (int mt = 0; mt < 4; mt++)
#pragma unroll
                for (int nt = 0; nt < 4; nt++)
                    mma_bf16(c[mt][nt], af[mt], bf[nt]);
        }
        if (c0 + 1 < nch) {
            int nb = (c0 + 1) & 1;
#pragma unroll
            for (int r = 0; r < 2; r++) {
                uint32_t* pa = &As[nb][arow + r * 64][apc];
                pa[0] = pack_bf16(ra[r][0].x, ra[r][0].y);
                pa[1] = pack_bf16(ra[r][0].z, ra[r][0].w);
                pa[2] = pack_bf16(ra[r][1].x, ra[r][1].y);
                pa[3] = pack_bf16(ra[r][1].z, ra[r][1].w);
            }
#pragma unroll
            for (int s = 0; s < 2; s++) {
                uint32_t* pb = &Bs[nb][bk2 + s * 8][bcol];
                pb[0] = pack_bf16(rb[s][0].x, rb[s][1].x);
                pb[1] = pack_bf16(rb[s][0].y, rb[s][1].y);
                pb[2] = pack_bf16(rb[s][0].z, rb[s][1].z);
                pb[3] = pack_bf16(rb[s][0].w, rb[s][1].w);
            }
            __syncthreads();
        }
    }

    // epilogue: store C (bf16) + fused attention-dot partials (fp32)
#pragma unroll
    for (int mt = 0; mt < 4; mt++) {
        int row = m0 + wm * 64 + mt * 16 + g;
#pragma unroll
        for (int nt = 0; nt < 4; nt++) {
            int col = wn * 32 + nt * 8 + kk * 2;
            if (row < M)
                *(__nv_bfloat162*)&C[(size_t)row * 128 + col] =
                    __floats2bfloat162_rn(c[mt][nt][0], c[mt][nt][1]);
            if (row + 8 < M)
                *(__nv_bfloat162*)&C[(size_t)(row + 8) * 128 + col] =
                    __floats2bfloat162_rn(c[mt][nt][2], c[mt][nt][3]);
        }
#pragma unroll
        for (int half = 0; half < 2; half++) {
            float ps = 0.f, pd = 0.f;
#pragma unroll
            for (int nt = 0; nt < 4; nt++) {
#pragma unroll
                for (int i = 0; i < 2; i++) {
                    int col = wn * 32 + nt * 8 + kk * 2 + i;
                    float v = c[mt][nt][half * 2 + i];
                    ps += v * s_av[0][col];
                    pd += v * s_av[1][col];
                }
            }
            ps += __shfl_xor_sync(0xFFFFFFFF, ps, 1);
            ps += __shfl_xor_sync(0xFFFFFFFF, ps, 2);
            pd += __shfl_xor_sync(0xFFFFFFFF, pd, 1);
            pd += __shfl_xor_sync(0xFFFFFFFF, pd, 2);
            if (kk == 0) {
                int lr = wm * 64 + mt * 16 + g + half * 8;
                atomicAdd(&s_pa[lr][0], ps);
                atomicAdd(&s_pa[lr][1], pd);
            }
        }
    }
    __syncthreads();
    if (tid < 128 && m0 + tid < M) {
        g_as[m0 + tid] = s_pa[tid][0];
        g_ad[m0 + tid] = s_pa[tid][1];
    }
}

// plain GEMM kernel (layer 2)
__global__ __launch_bounds__(256) void k_gemm_tc(const float* __restrict__ A,
                                                 const float* __restrict__ B,
                                                 __nv_bfloat16* __restrict__ C,
                                                 const float* __restrict__ a_src,
                                                 const float* __restrict__ a_dst,
                                                 int M, int K) {
    gemm_body(blockIdx.x * BM, A, B, C, a_src, a_dst, M, K);
}

// fused GEMM1 + CSR fill (block-partitioned; fill has no atomics thanks to g_pos)
__global__ __launch_bounds__(256) void k_gemm_fill(const float* __restrict__ A,
                                                   const float* __restrict__ B,
                                                   __nv_bfloat16* __restrict__ C,
                                                   const float* __restrict__ a_src,
                                                   const float* __restrict__ a_dst,
                                                   int M, int K,
                                                   const int* __restrict__ src,
                                                   const int* __restrict__ dst) {
    if (blockIdx.x < GEMM_BLOCKS) {
        gemm_body(blockIdx.x * BM, A, B, C, a_src, a_dst, M, K);
    } else {
        int t = (blockIdx.x - GEMM_BLOCKS) * blockDim.x + threadIdx.x;
        if (t < NN) {
            g_csr_src[g_rowptr[t]] = t;                       // self loop first
        } else if (t < NN + EE) {
            int e = t - NN;
            int d = dst[e];
            g_csr_src[g_rowptr[d] + 1 + g_pos[e]] = src[e];   // pure store
        }
    }
}

__device__ __forceinline__ float lrelu(float x) {
    return x > 0.f ? x : NEG_SLOPE * x;
}

// ---------------- single-pass aggregation, smem-staged weights -----------------
__global__ __launch_bounds__(256) void k_aggregate(const __nv_bfloat16* __restrict__ h,
                                                   const float* __restrict__ b,
                                                   float* __restrict__ out) {
    __shared__ int   sh_s[8][32];
    __shared__ float sh_w[8][32];
    int warp = threadIdx.x >> 5;
    int lane = threadIdx.x & 31;
    int v = (blockIdx.x * blockDim.x + threadIdx.x) >> 5;
    if (v >= NN) return;
    int beg = g_rowptr[v];
    int end = g_rowptr[v + 1];
    float adv = g_ad[v];

    float4 acc = make_float4(0.f, 0.f, 0.f, 0.f);
    float den_p = 0.f;
    for (int c0 = beg; c0 < end; c0 += 32) {
        int n = min(32, end - c0);
        int s = 0;
        float w = 0.f;
        if (lane < n) {
            s = g_csr_src[c0 + lane];
            w = __expf(lrelu(__ldg(&g_as[s]) + adv));
        }
        sh_s[warp][lane] = s;
        sh_w[warp][lane] = w;
        __syncwarp();
        den_p += w;
#pragma unroll 4
        for (int j = 0; j < n; j++) {
            float wb = sh_w[warp][j];
            int sb = sh_s[warp][j];
            uint2 u = *(const uint2*)&h[(size_t)sb * 128 + lane * 4];
            float2 f0 = __bfloat1622float2(*(__nv_bfloat162*)&u.x);
            float2 f1 = __bfloat1622float2(*(__nv_bfloat162*)&u.y);
            acc.x += wb * f0.x;
            acc.y += wb * f0.y;
            acc.z += wb * f1.x;
            acc.w += wb * f1.y;
        }
        __syncwarp();
    }
#pragma unroll
    for (int off = 16; off > 0; off >>= 1)
        den_p += __shfl_xor_sync(0xFFFFFFFF, den_p, off);

    float inv = 1.f / den_p;
    float4 b4 = *(const float4*)&b[lane * 4];
    float4 o = make_float4(acc.x * inv + b4.x, acc.y * inv + b4.y,
                           acc.z * inv + b4.z, acc.w * inv + b4.w);
    *(float4*)&out[(size_t)v * 128 + lane * 4] = o;
}

// ---------------- fused pooling + g-feature + head (block per graph) -----------
__device__ __forceinline__ int lower_bound_i(const int* a, int n, int key) {
    int lo = 0, hi = n;
    while (lo < hi) {
        int mid = (lo + hi) >> 1;
        if (a[mid] < key) lo = mid + 1;
        else hi = mid;
    }
    return lo;
}

__global__ __launch_bounds__(128) void k_poolhead(const float* __restrict__ x,
                                                  const int* __restrict__ batch,
                                                  const float* __restrict__ gfeat,
                                                  const float* __restrict__ Wg,
                                                  const float* __restrict__ bg,
                                                  const float* __restrict__ Wo,
                                                  const float* __restrict__ bo,
                                                  float* __restrict__ out) {
    int g = blockIdx.x;
    int f = threadIdx.x;
    __shared__ int s_lo, s_hi;
    __shared__ float sgf[GF];
    __shared__ float red[2][4];
    if (f == 0) s_lo = lower_bound_i(batch, NN, g);
    if (f == 1) s_hi = lower_bound_i(batch, NN, g + 1);
    if (f >= 64 && f < 64 + GF) sgf[f - 64] = gfeat[g * GF + (f - 64)];
    __syncthreads();
    int lo = s_lo, hi = s_hi;

    float s = 0.f, mx = -1e30f;
    for (int i = lo; i < hi; i++) {
        float v = x[(size_t)i * 128 + f];
        s += v;
        mx = fmaxf(mx, v);
    }
    int cnt = hi - lo;
    float mean = s / (float)max(cnt, 1);
    mx = (cnt > 0) ? mx : 0.f;

    float gft = bg[f];
#pragma unroll
    for (int k = 0; k < GF; k++)
        gft += sgf[k] * Wg[k * EMB + f];

    float c0 = mean * Wo[f * 2 + 0] + mx * Wo[(128 + f) * 2 + 0] + gft * Wo[(256 + f) * 2 + 0];
    float c1 = mean * Wo[f * 2 + 1] + mx * Wo[(128 + f) * 2 + 1] + gft * Wo[(256 + f) * 2 + 1];
#pragma unroll
    for (int off = 16; off > 0; off >>= 1) {
        c0 += __shfl_xor_sync(0xFFFFFFFF, c0, off);
        c1 += __shfl_xor_sync(0xFFFFFFFF, c1, off);
    }
    int lane = f & 31, w = f >> 5;
    if (lane == 0) { red[0][w] = c0; red[1][w] = c1; }
    __syncthreads();
    if (f == 0) {
        float l0 = red[0][0] + red[0][1] + red[0][2] + red[0][3] + bo[0];
        float l1 = red[1][0] + red[1][1] + red[1][2] + red[1][3] + bo[1];
        float m = fmaxf(l0, l1);
        float lse = m + logf(expf(l0 - m) + expf(l1 - m));
        out[g * 2 + 0] = l0 - lse;
        out[g * 2 + 1] = l1 - lse;
    }
}

// ---------------- launch --------------------------------------------------------
extern "C" void kernel_launch(void* const* d_in, const int* in_sizes, int n_in,
                              void* d_out, int out_size) {
    const float* x      = (const float*)d_in[0];
    const int*   edges  = (const int*)d_in[1];
    const int*   batch  = (const int*)d_in[2];
    const float* gfeat  = (const float*)d_in[3];
    const float* W1     = (const float*)d_in[4];
    const float* a1s    = (const float*)d_in[5];
    const float* a1d    = (const float*)d_in[6];
    const float* b1     = (const float*)d_in[7];
    const float* W2     = (const float*)d_in[8];
    const float* a2s    = (const float*)d_in[9];
    const float* a2d    = (const float*)d_in[10];
    const float* b2     = (const float*)d_in[11];
    const float* Wg     = (const float*)d_in[12];
    const float* bg     = (const float*)d_in[13];
    const float* Wo     = (const float*)d_in[14];
    const float* bo     = (const float*)d_in[15];
    float* out = (float*)d_out;

    const int* src = edges;
    const int* dst = edges + EE;

    __nv_bfloat16* d_hb; cudaGetSymbolAddress((void**)&d_hb, g_hb);
    float* d_x2; cudaGetSymbolAddress((void**)&d_x2, g_x2);

    // CSR prefix (zero -> hist(+pos) -> scan1 -> scan3)
    k_zero<<<(NN / 4 + 255) / 256, 256>>>();
    k_hist<<<(EE + 255) / 256, 256>>>(dst);
    k_scan1<<<NBLK, SCAN_B>>>();
    k_scan3<<<(NN + 255) / 256, 256>>>();

    int warp_blocks = (NN * 32 + 255) / 256;

    // fused: GEMM1 (h, as, ad) + CSR fill (atomic-free, hidden under GEMM)
    k_gemm_fill<<<GEMM_BLOCKS + FILL_BLOCKS, 256>>>(x, W1, d_hb, a1s, a1d, NN, FIN, src, dst);
    k_aggregate<<<warp_blocks, 256>>>(d_hb, b1, d_x2);

    // layer 2
    k_gemm_tc<<<GEMM_BLOCKS, 256>>>(d_x2, W2, d_hb, a2s, a2d, NN, EMB);
    k_aggregate<<<warp_blocks, 256>>>(d_hb, b2, d_x2);

    // fused pooling + g-feature + head
    k_poolhead<<<GG, 128>>>(d_x2, batch, gfeat, Wg, bg, Wo, bo, out);
}